// round 5
// baseline (speedup 1.0000x reference)
#include <cuda_runtime.h>

// Problem constants
#define NB 8
#define NN 1024
#define NC 768
#define NH 12
#define ND 64
#define C3 2304                  // 3*NC
#define SCALE 0.125f             // ND^-0.5

#define OUT_ELEMS  (6291456)     // 8*1024*768
#define ATTN_ELEMS (100663296)   // 8*12*1024*1024
#define TOTAL_ELEMS (OUT_ELEMS + ATTN_ELEMS)  // 106954752 (fits int)

// Per-batch scratch only: total ~16 MB of __device__ bss.
__device__ float g_q[NH * NN * ND];    // 786432 floats
__device__ float g_k[NH * NN * ND];
__device__ float g_v[NH * NN * ND];
__device__ float g_ob[NN * NC];        // per-batch O in [N, C] layout
__device__ float g_ph[NN * NN];        // fallback probs for one head

__device__ __forceinline__ float4 ld4(const float* p) { return *(const float4*)p; }

// ---------------------------------------------------------------------------
// QKV projection for one batch: qkv[m, j] = x_b[m,:] . w_qkv[j,:]
// 128x128 tile, BK=8, 256 threads, 8x8 per thread. Scatter into g_q/g_k/g_v
// with per-batch layout [H][N][D]. Grid (18, 8).
// ---------------------------------------------------------------------------
__global__ __launch_bounds__(256)
void qkv_gemm(const float* __restrict__ x, const float* __restrict__ w, int b0)
{
    __shared__ float As[8][128];
    __shared__ float Bs[8][128];

    const int tid = threadIdx.x;
    const int m0 = blockIdx.y * 128;
    const int n0 = blockIdx.x * 128;
    const float* A = x + (size_t)b0 * NN * NC;

    const int lrow = tid >> 1;
    const int lkq  = (tid & 1) * 4;
    const float* Ap = A + (size_t)(m0 + lrow) * NC + lkq;
    const float* Wp = w + (size_t)(n0 + lrow) * NC + lkq;

    const int ty = tid >> 4, tx = tid & 15;
    const int r0 = ty * 8, c0 = tx * 8;

    float acc[8][8];
#pragma unroll
    for (int i = 0; i < 8; ++i)
#pragma unroll
        for (int j = 0; j < 8; ++j) acc[i][j] = 0.0f;

    for (int k0 = 0; k0 < NC; k0 += 8) {
        float4 a4 = ld4(Ap + k0);
        float4 b4 = ld4(Wp + k0);
        __syncthreads();
        As[lkq + 0][lrow] = a4.x; As[lkq + 1][lrow] = a4.y;
        As[lkq + 2][lrow] = a4.z; As[lkq + 3][lrow] = a4.w;
        Bs[lkq + 0][lrow] = b4.x; Bs[lkq + 1][lrow] = b4.y;
        Bs[lkq + 2][lrow] = b4.z; Bs[lkq + 3][lrow] = b4.w;
        __syncthreads();
#pragma unroll
        for (int kk = 0; kk < 8; ++kk) {
            __align__(16) float ar[8], br[8];
            *(float4*)&ar[0] = *(const float4*)&As[kk][r0];
            *(float4*)&ar[4] = *(const float4*)&As[kk][r0 + 4];
            *(float4*)&br[0] = *(const float4*)&Bs[kk][c0];
            *(float4*)&br[4] = *(const float4*)&Bs[kk][c0 + 4];
#pragma unroll
            for (int i = 0; i < 8; ++i)
#pragma unroll
                for (int j = 0; j < 8; ++j)
                    acc[i][j] = fmaf(ar[i], br[j], acc[i][j]);
        }
    }

    // col j = s*768 + h*64 + d. 128-wide tiles never straddle s (768%128==0);
    // 8-wide thread tiles never straddle h (64).
    const int s    = n0 / NC;
    const int rem0 = (n0 % NC) + c0;
    const int h    = rem0 >> 6;
    const int d    = rem0 & 63;
    float* dst = (s == 0) ? g_q : (s == 1) ? g_k : g_v;
#pragma unroll
    for (int i = 0; i < 8; ++i) {
        const int nn = m0 + r0 + i;
        float* p = dst + (((size_t)h * NN + nn) * ND + d);
        *(float4*)(p)     = make_float4(acc[i][0], acc[i][1], acc[i][2], acc[i][3]);
        *(float4*)(p + 4) = make_float4(acc[i][4], acc[i][5], acc[i][6], acc[i][7]);
    }
}

// ---------------------------------------------------------------------------
// Scores: P[hz][n][m] = SCALE * q[h0+hz][n][:] . k[h0+hz][m][:]
// probs==nullptr -> use g_ph scratch (fallback path, nh=1).
// Grid (8, 8, nh). 128x128 tile, K=64 fully unrolled.
// ---------------------------------------------------------------------------
__global__ __launch_bounds__(256)
void score_gemm(float* __restrict__ probs, int h0)
{
    __shared__ float As[8][128];
    __shared__ float Bs[8][128];

    const int tid = threadIdx.x;
    const int m0 = blockIdx.y * 128;     // query rows
    const int n0 = blockIdx.x * 128;     // key rows
    const int hz = blockIdx.z;
    const int h  = h0 + hz;

    const float* A = g_q + (size_t)h * NN * ND;
    const float* W = g_k + (size_t)h * NN * ND;
    float* out = probs ? probs + (size_t)hz * NN * NN : g_ph;

    const int lrow = tid >> 1;
    const int lkq  = (tid & 1) * 4;
    const float* Ap = A + (size_t)(m0 + lrow) * ND + lkq;
    const float* Wp = W + (size_t)(n0 + lrow) * ND + lkq;

    const int ty = tid >> 4, tx = tid & 15;
    const int r0 = ty * 8, c0 = tx * 8;

    float acc[8][8];
#pragma unroll
    for (int i = 0; i < 8; ++i)
#pragma unroll
        for (int j = 0; j < 8; ++j) acc[i][j] = 0.0f;

#pragma unroll
    for (int k0 = 0; k0 < ND; k0 += 8) {
        float4 a4 = ld4(Ap + k0);
        float4 b4 = ld4(Wp + k0);
        __syncthreads();
        As[lkq + 0][lrow] = a4.x; As[lkq + 1][lrow] = a4.y;
        As[lkq + 2][lrow] = a4.z; As[lkq + 3][lrow] = a4.w;
        Bs[lkq + 0][lrow] = b4.x; Bs[lkq + 1][lrow] = b4.y;
        Bs[lkq + 2][lrow] = b4.z; Bs[lkq + 3][lrow] = b4.w;
        __syncthreads();
#pragma unroll
        for (int kk = 0; kk < 8; ++kk) {
            __align__(16) float ar[8], br[8];
            *(float4*)&ar[0] = *(const float4*)&As[kk][r0];
            *(float4*)&ar[4] = *(const float4*)&As[kk][r0 + 4];
            *(float4*)&br[0] = *(const float4*)&Bs[kk][c0];
            *(float4*)&br[4] = *(const float4*)&Bs[kk][c0 + 4];
#pragma unroll
            for (int i = 0; i < 8; ++i)
#pragma unroll
                for (int j = 0; j < 8; ++j)
                    acc[i][j] = fmaf(ar[i], br[j], acc[i][j]);
        }
    }

#pragma unroll
    for (int i = 0; i < 8; ++i) {
        float* p = out + (size_t)(m0 + r0 + i) * NN + n0 + c0;
        *(float4*)(p)     = make_float4(acc[i][0] * SCALE, acc[i][1] * SCALE,
                                        acc[i][2] * SCALE, acc[i][3] * SCALE);
        *(float4*)(p + 4) = make_float4(acc[i][4] * SCALE, acc[i][5] * SCALE,
                                        acc[i][6] * SCALE, acc[i][7] * SCALE);
    }
}

// ---------------------------------------------------------------------------
// Softmax in place. Warp per row, register-resident. Grid (128, nh).
// ---------------------------------------------------------------------------
__global__ __launch_bounds__(256)
void softmax_kernel(float* __restrict__ probs)
{
    const int w    = threadIdx.x >> 5;
    const int lane = threadIdx.x & 31;
    const int hz   = blockIdx.y;
    const int r    = blockIdx.x * 8 + w;

    float* base = probs ? probs + (size_t)hz * NN * NN : g_ph;
    float4* row = (float4*)(base + (size_t)r * NN);

    float4 v[8];
#pragma unroll
    for (int t = 0; t < 8; ++t) v[t] = row[lane + t * 32];

    float mx = -1e30f;
#pragma unroll
    for (int t = 0; t < 8; ++t)
        mx = fmaxf(mx, fmaxf(fmaxf(v[t].x, v[t].y), fmaxf(v[t].z, v[t].w)));
#pragma unroll
    for (int off = 16; off >= 1; off >>= 1)
        mx = fmaxf(mx, __shfl_xor_sync(0xffffffffu, mx, off));

    float sum = 0.0f;
#pragma unroll
    for (int t = 0; t < 8; ++t) {
        v[t].x = __expf(v[t].x - mx); v[t].y = __expf(v[t].y - mx);
        v[t].z = __expf(v[t].z - mx); v[t].w = __expf(v[t].w - mx);
        sum += v[t].x + v[t].y + v[t].z + v[t].w;
    }
#pragma unroll
    for (int off = 16; off >= 1; off >>= 1)
        sum += __shfl_xor_sync(0xffffffffu, sum, off);

    const float inv = 1.0f / sum;
#pragma unroll
    for (int t = 0; t < 8; ++t) {
        v[t].x *= inv; v[t].y *= inv; v[t].z *= inv; v[t].w *= inv;
        row[lane + t * 32] = v[t];
    }
}

// ---------------------------------------------------------------------------
// PV: g_ob[n][h*64+d] = sum_m P[hz][n][m] * v[h0+hz][m][d]. Grid (8, nh).
// Tile 128 rows x 64 d, BK=32. Static smem ~25KB. Thread: 4 rows x 8 cols.
// ---------------------------------------------------------------------------
__global__ __launch_bounds__(256)
void pv_gemm(const float* __restrict__ probs, int h0)
{
    __shared__ float Ps[128][33];
    __shared__ float Vs[32][64];

    const int tid = threadIdx.x;
    const int n0 = blockIdx.x * 128;
    const int hz = blockIdx.y;
    const int h  = h0 + hz;

    const float* base = probs ? probs + (size_t)hz * NN * NN : g_ph;
    const float* P = base + (size_t)n0 * NN;
    const float* V = g_v + (size_t)h * NN * ND;

    const int tr = tid >> 3;
    const int tc = tid & 7;
    const int r0 = tr * 4, c0 = tc * 8;

    float acc[4][8];
#pragma unroll
    for (int i = 0; i < 4; ++i)
#pragma unroll
        for (int j = 0; j < 8; ++j) acc[i][j] = 0.0f;

    for (int mt = 0; mt < 32; ++mt) {
        __syncthreads();
#pragma unroll
        for (int it = 0; it < 4; ++it) {
            const int q = tid + it * 256;
            const int row = q >> 3;
            const int mq  = q & 7;
            float4 f = ld4(P + (size_t)row * NN + mt * 32 + mq * 4);
            Ps[row][mq * 4 + 0] = f.x; Ps[row][mq * 4 + 1] = f.y;
            Ps[row][mq * 4 + 2] = f.z; Ps[row][mq * 4 + 3] = f.w;
        }
#pragma unroll
        for (int it = 0; it < 2; ++it) {
            const int q = tid + it * 256;
            const int rr = q >> 4;
            const int dq = q & 15;
            *(float4*)&Vs[rr][dq * 4] = ld4(V + (size_t)(mt * 32 + rr) * ND + dq * 4);
        }
        __syncthreads();

#pragma unroll
        for (int kk = 0; kk < 32; ++kk) {
            float a0 = Ps[r0 + 0][kk];
            float a1 = Ps[r0 + 1][kk];
            float a2 = Ps[r0 + 2][kk];
            float a3 = Ps[r0 + 3][kk];
            __align__(16) float bv[8];
            *(float4*)&bv[0] = *(const float4*)&Vs[kk][c0];
            *(float4*)&bv[4] = *(const float4*)&Vs[kk][c0 + 4];
#pragma unroll
            for (int j = 0; j < 8; ++j) {
                acc[0][j] = fmaf(a0, bv[j], acc[0][j]);
                acc[1][j] = fmaf(a1, bv[j], acc[1][j]);
                acc[2][j] = fmaf(a2, bv[j], acc[2][j]);
                acc[3][j] = fmaf(a3, bv[j], acc[3][j]);
            }
        }
    }

#pragma unroll
    for (int i = 0; i < 4; ++i) {
        float* p = g_ob + ((size_t)(n0 + r0 + i)) * NC + h * ND + c0;
        *(float4*)(p)     = make_float4(acc[i][0], acc[i][1], acc[i][2], acc[i][3]);
        *(float4*)(p + 4) = make_float4(acc[i][4], acc[i][5], acc[i][6], acc[i][7]);
    }
}

// ---------------------------------------------------------------------------
// Output projection for one batch: out_b = g_ob @ w_proj^T + bias. Grid (6, 8).
// ---------------------------------------------------------------------------
__global__ __launch_bounds__(256)
void proj_gemm(const float* __restrict__ w, const float* __restrict__ bias,
               float* __restrict__ out, int b0)
{
    __shared__ float As[8][128];
    __shared__ float Bs[8][128];

    const int tid = threadIdx.x;
    const int m0 = blockIdx.y * 128;
    const int n0 = blockIdx.x * 128;

    const int lrow = tid >> 1;
    const int lkq  = (tid & 1) * 4;
    const float* Ap = g_ob + (size_t)(m0 + lrow) * NC + lkq;
    const float* Wp = w + (size_t)(n0 + lrow) * NC + lkq;

    const int ty = tid >> 4, tx = tid & 15;
    const int r0 = ty * 8, c0 = tx * 8;

    float acc[8][8];
#pragma unroll
    for (int i = 0; i < 8; ++i)
#pragma unroll
        for (int j = 0; j < 8; ++j) acc[i][j] = 0.0f;

    for (int k0 = 0; k0 < NC; k0 += 8) {
        float4 a4 = ld4(Ap + k0);
        float4 b4 = ld4(Wp + k0);
        __syncthreads();
        As[lkq + 0][lrow] = a4.x; As[lkq + 1][lrow] = a4.y;
        As[lkq + 2][lrow] = a4.z; As[lkq + 3][lrow] = a4.w;
        Bs[lkq + 0][lrow] = b4.x; Bs[lkq + 1][lrow] = b4.y;
        Bs[lkq + 2][lrow] = b4.z; Bs[lkq + 3][lrow] = b4.w;
        __syncthreads();
#pragma unroll
        for (int kk = 0; kk < 8; ++kk) {
            __align__(16) float ar[8], br[8];
            *(float4*)&ar[0] = *(const float4*)&As[kk][r0];
            *(float4*)&ar[4] = *(const float4*)&As[kk][r0 + 4];
            *(float4*)&br[0] = *(const float4*)&Bs[kk][c0];
            *(float4*)&br[4] = *(const float4*)&Bs[kk][c0 + 4];
#pragma unroll
            for (int i = 0; i < 8; ++i)
#pragma unroll
                for (int j = 0; j < 8; ++j)
                    acc[i][j] = fmaf(ar[i], br[j], acc[i][j]);
        }
    }

    __align__(16) float bb0[8];
    *(float4*)&bb0[0] = ld4(bias + n0 + c0);
    *(float4*)&bb0[4] = ld4(bias + n0 + c0 + 4);
    float* ob = out + (size_t)b0 * NN * NC;
#pragma unroll
    for (int i = 0; i < 8; ++i) {
        float* p = ob + (size_t)(m0 + r0 + i) * NC + n0 + c0;
        *(float4*)(p)     = make_float4(acc[i][0] + bb0[0], acc[i][1] + bb0[1],
                                        acc[i][2] + bb0[2], acc[i][3] + bb0[3]);
        *(float4*)(p + 4) = make_float4(acc[i][4] + bb0[4], acc[i][5] + bb0[5],
                                        acc[i][6] + bb0[6], acc[i][7] + bb0[7]);
    }
}

// ---------------------------------------------------------------------------
extern "C" void kernel_launch(void* const* d_in, const int* in_sizes, int n_in,
                              void* d_out, int out_size)
{
    // Positional per metadata order, cross-checked by unique sizes
    // (element counts and byte counts both accepted).
    const float* x      = (n_in > 0) ? (const float*)d_in[0] : nullptr;
    const float* w_qkv  = (n_in > 1) ? (const float*)d_in[1] : nullptr;
    const float* w_proj = (n_in > 2) ? (const float*)d_in[2] : nullptr;
    const float* b_proj = (n_in > 3) ? (const float*)d_in[3] : nullptr;
    for (int i = 0; i < n_in; ++i) {
        const long long s = in_sizes[i];
        if (s == 6291456LL || s == 25165824LL) x      = (const float*)d_in[i];
        else if (s == 1769472LL || s == 7077888LL) w_qkv  = (const float*)d_in[i];
        else if (s == 589824LL  || s == 2359296LL) w_proj = (const float*)d_in[i];
        else if (s == 768LL     || s == 3072LL)    b_proj = (const float*)d_in[i];
    }
    if (!x || !w_qkv || !w_proj || !b_proj) return;
    if (out_size < OUT_ELEMS) return;

    float* out  = (float*)d_out;
    const bool have_attn = (out_size >= TOTAL_ELEMS);
    float* attn = have_attn ? out + OUT_ELEMS : nullptr;

    for (int b = 0; b < NB; ++b) {
        qkv_gemm<<<dim3(C3 / 128, NN / 128), 256>>>(x, w_qkv, b);
        if (have_attn) {
            float* pb = attn + (size_t)b * NH * NN * NN;
            score_gemm   <<<dim3(NN / 128, NN / 128, NH), 256>>>(pb, 0);
            softmax_kernel<<<dim3(NN / 8, NH), 256>>>(pb);
            pv_gemm      <<<dim3(NN / 128, NH), 256>>>(pb, 0);
        } else {
            // No room for attn in d_out: run per-head via g_ph scratch,
            // never writing outside [0, out_size).
            for (int h = 0; h < NH; ++h) {
                score_gemm   <<<dim3(NN / 128, NN / 128, 1), 256>>>(nullptr, h);
                softmax_kernel<<<dim3(NN / 8, 1), 256>>>(nullptr);
                pv_gemm      <<<dim3(NN / 128, 1), 256>>>(nullptr, h);
            }
        }
        proj_gemm<<<dim3(NC / 128, NN / 128), 256>>>(w_proj, b_proj, out, b);
    }
}

// round 8
// speedup vs baseline: 1.7915x; 1.7915x over previous
#include <cuda_runtime.h>

// Problem constants
#define NB 8
#define NN 1024
#define NC 768
#define NH 12
#define ND 64
#define C3 2304
#define MROWS 8192
#define SCALE 0.125f

#define OUT_ELEMS  6291456      // 8*1024*768
#define ATTN_ELEMS 100663296    // 8*12*1024*1024
#define TOTAL_ELEMS 106954752
#define BHD 65536               // NN*ND   (per batch-head q/k/v)
#define PSTRIDE 1048576         // NN*NN   (per batch-head probs)
#define QKV_E 6291456           // NB*NH*NN*ND (one full q, k, or v)
#define SCR_BASE 75497472       // 72*PSTRIDE: scratch starts after probs of b=0..5

// bss scratch: 24 + 3*6 = 42 MB
__device__ float g_o [(size_t)MROWS * NC];     // O in [B,N,C] layout
__device__ float g_q2[2 * NH * NN * ND];       // q/k/v stash for batches 6,7
__device__ float g_k2[2 * NH * NN * ND];
__device__ float g_v2[2 * NH * NN * ND];

__device__ __forceinline__ float4 ld4(const float* p) { return *(const float4*)p; }

// ---------------------------------------------------------------------------
// QKV projection, ALL batches: C[8192, 2304] = x @ w_qkv^T, scattered into
// qs/ks/vs with [bh][n][d] layout. 128x128 tile, BK=16, software-pipelined.
// Grid (18, 64), 256 threads, 8x8 micro-tile.
// ---------------------------------------------------------------------------
__global__ __launch_bounds__(256, 2)
void qkv_all(const float* __restrict__ x, const float* __restrict__ w,
             float* __restrict__ qs, float* __restrict__ ks, float* __restrict__ vs)
{
    __shared__ float As[16][128];
    __shared__ float Bs[16][128];

    const int tid = threadIdx.x;
    const int m0 = blockIdx.y * 128;
    const int n0 = blockIdx.x * 128;

    const int lrow = tid >> 1;           // 0..127
    const int lk8  = (tid & 1) * 8;      // 0 or 8
    const float* Ap = x + (size_t)(m0 + lrow) * NC + lk8;
    const float* Wp = w + (size_t)(n0 + lrow) * NC + lk8;

    const int ty = tid >> 4, tx = tid & 15;
    const int r0 = ty * 8, c0 = tx * 8;

    float acc[8][8];
#pragma unroll
    for (int i = 0; i < 8; ++i)
#pragma unroll
        for (int j = 0; j < 8; ++j) acc[i][j] = 0.0f;

    float4 a0 = ld4(Ap), a1 = ld4(Ap + 4);
    float4 b0 = ld4(Wp), b1 = ld4(Wp + 4);

    for (int k0 = 0; k0 < NC; k0 += 16) {
        __syncthreads();
        As[lk8+0][lrow]=a0.x; As[lk8+1][lrow]=a0.y; As[lk8+2][lrow]=a0.z; As[lk8+3][lrow]=a0.w;
        As[lk8+4][lrow]=a1.x; As[lk8+5][lrow]=a1.y; As[lk8+6][lrow]=a1.z; As[lk8+7][lrow]=a1.w;
        Bs[lk8+0][lrow]=b0.x; Bs[lk8+1][lrow]=b0.y; Bs[lk8+2][lrow]=b0.z; Bs[lk8+3][lrow]=b0.w;
        Bs[lk8+4][lrow]=b1.x; Bs[lk8+5][lrow]=b1.y; Bs[lk8+6][lrow]=b1.z; Bs[lk8+7][lrow]=b1.w;
        __syncthreads();
        if (k0 + 16 < NC) {                       // prefetch next tile
            a0 = ld4(Ap + k0 + 16); a1 = ld4(Ap + k0 + 20);
            b0 = ld4(Wp + k0 + 16); b1 = ld4(Wp + k0 + 20);
        }
#pragma unroll
        for (int kk = 0; kk < 16; ++kk) {
            __align__(16) float ar[8], br[8];
            *(float4*)&ar[0] = *(const float4*)&As[kk][r0];
            *(float4*)&ar[4] = *(const float4*)&As[kk][r0 + 4];
            *(float4*)&br[0] = *(const float4*)&Bs[kk][c0];
            *(float4*)&br[4] = *(const float4*)&Bs[kk][c0 + 4];
#pragma unroll
            for (int i = 0; i < 8; ++i)
#pragma unroll
                for (int j = 0; j < 8; ++j)
                    acc[i][j] = fmaf(ar[i], br[j], acc[i][j]);
        }
    }

    // col j = s*768 + h*64 + d; 128-wide tiles never straddle s (768%128==0),
    // 8-wide thread tiles never straddle h (64).
    const int s    = n0 / NC;
    const int rem0 = (n0 % NC) + c0;
    const int h    = rem0 >> 6;
    const int d    = rem0 & 63;
    float* dst = (s == 0) ? qs : (s == 1) ? ks : vs;
#pragma unroll
    for (int i = 0; i < 8; ++i) {
        const int gi = m0 + r0 + i;
        const int b  = gi >> 10;
        const int nn = gi & 1023;
        float* p = dst + (((size_t)(b * NH + h) * NN + nn) * ND + d);
        *(float4*)(p)     = make_float4(acc[i][0], acc[i][1], acc[i][2], acc[i][3]);
        *(float4*)(p + 4) = make_float4(acc[i][4], acc[i][5], acc[i][6], acc[i][7]);
    }
}

// ---------------------------------------------------------------------------
// Stash q/k/v of batches 6,7 (bh 72..95) into bss before probs overwrite them.
// g_q2/g_k2/g_v2 referenced in DEVICE code (correct symbol resolution).
// ---------------------------------------------------------------------------
__global__ __launch_bounds__(256)
void copy67(const float4* __restrict__ qs, const float4* __restrict__ ks,
            const float4* __restrict__ vs)
{
    const int n4 = 2 * NH * NN * ND / 4;          // 393216
    for (int i = blockIdx.x * blockDim.x + threadIdx.x; i < n4;
         i += gridDim.x * blockDim.x) {
        ((float4*)g_q2)[i] = qs[i];
        ((float4*)g_k2)[i] = ks[i];
        ((float4*)g_v2)[i] = vs[i];
    }
}

// ---------------------------------------------------------------------------
// Scores for Z batch-heads: P[z][n][m] = SCALE * q[z][n][:] . k[z][m][:]
// stash=1 -> q/k come from g_q2/g_k2 (device-side symbol refs).
// Grid (8, 8, Z), 256 threads, 128x128 tile, K=64 (4 pipelined BK=16 iters).
// ---------------------------------------------------------------------------
__global__ __launch_bounds__(256, 2)
void score_all(const float* __restrict__ qbase, const float* __restrict__ kbase,
               float* __restrict__ probs_base, int stash)
{
    __shared__ float As[16][128];
    __shared__ float Bs[16][128];

    const int tid = threadIdx.x;
    const int m0 = blockIdx.y * 128;
    const int n0 = blockIdx.x * 128;
    const int z  = blockIdx.z;

    const float* A = (stash ? (const float*)g_q2 : qbase) + (size_t)z * BHD;
    const float* W = (stash ? (const float*)g_k2 : kbase) + (size_t)z * BHD;
    float* out = probs_base + (size_t)z * PSTRIDE;

    const int lrow = tid >> 1;
    const int lk8  = (tid & 1) * 8;
    const float* Ap = A + (size_t)(m0 + lrow) * ND + lk8;
    const float* Wp = W + (size_t)(n0 + lrow) * ND + lk8;

    const int ty = tid >> 4, tx = tid & 15;
    const int r0 = ty * 8, c0 = tx * 8;

    float acc[8][8];
#pragma unroll
    for (int i = 0; i < 8; ++i)
#pragma unroll
        for (int j = 0; j < 8; ++j) acc[i][j] = 0.0f;

    float4 a0 = ld4(Ap), a1 = ld4(Ap + 4);
    float4 b0 = ld4(Wp), b1 = ld4(Wp + 4);

#pragma unroll
    for (int k0 = 0; k0 < ND; k0 += 16) {
        __syncthreads();
        As[lk8+0][lrow]=a0.x; As[lk8+1][lrow]=a0.y; As[lk8+2][lrow]=a0.z; As[lk8+3][lrow]=a0.w;
        As[lk8+4][lrow]=a1.x; As[lk8+5][lrow]=a1.y; As[lk8+6][lrow]=a1.z; As[lk8+7][lrow]=a1.w;
        Bs[lk8+0][lrow]=b0.x; Bs[lk8+1][lrow]=b0.y; Bs[lk8+2][lrow]=b0.z; Bs[lk8+3][lrow]=b0.w;
        Bs[lk8+4][lrow]=b1.x; Bs[lk8+5][lrow]=b1.y; Bs[lk8+6][lrow]=b1.z; Bs[lk8+7][lrow]=b1.w;
        __syncthreads();
        if (k0 + 16 < ND) {
            a0 = ld4(Ap + k0 + 16); a1 = ld4(Ap + k0 + 20);
            b0 = ld4(Wp + k0 + 16); b1 = ld4(Wp + k0 + 20);
        }
#pragma unroll
        for (int kk = 0; kk < 16; ++kk) {
            __align__(16) float ar[8], br[8];
            *(float4*)&ar[0] = *(const float4*)&As[kk][r0];
            *(float4*)&ar[4] = *(const float4*)&As[kk][r0 + 4];
            *(float4*)&br[0] = *(const float4*)&Bs[kk][c0];
            *(float4*)&br[4] = *(const float4*)&Bs[kk][c0 + 4];
#pragma unroll
            for (int i = 0; i < 8; ++i)
#pragma unroll
                for (int j = 0; j < 8; ++j)
                    acc[i][j] = fmaf(ar[i], br[j], acc[i][j]);
        }
    }

#pragma unroll
    for (int i = 0; i < 8; ++i) {
        float* p = out + (size_t)(m0 + r0 + i) * NN + n0 + c0;
        *(float4*)(p)     = make_float4(acc[i][0]*SCALE, acc[i][1]*SCALE,
                                        acc[i][2]*SCALE, acc[i][3]*SCALE);
        *(float4*)(p + 4) = make_float4(acc[i][4]*SCALE, acc[i][5]*SCALE,
                                        acc[i][6]*SCALE, acc[i][7]*SCALE);
    }
}

// ---------------------------------------------------------------------------
// Softmax in place. Warp per row, register-resident. Grid (128, Z).
// ---------------------------------------------------------------------------
__global__ __launch_bounds__(256)
void softmax_all(float* __restrict__ probs_base)
{
    const int w    = threadIdx.x >> 5;
    const int lane = threadIdx.x & 31;
    const int z    = blockIdx.y;
    const int r    = blockIdx.x * 8 + w;

    float4* row = (float4*)(probs_base + (size_t)z * PSTRIDE + (size_t)r * NN);

    float4 v[8];
#pragma unroll
    for (int t = 0; t < 8; ++t) v[t] = row[lane + t * 32];

    float mx = -1e30f;
#pragma unroll
    for (int t = 0; t < 8; ++t)
        mx = fmaxf(mx, fmaxf(fmaxf(v[t].x, v[t].y), fmaxf(v[t].z, v[t].w)));
#pragma unroll
    for (int off = 16; off >= 1; off >>= 1)
        mx = fmaxf(mx, __shfl_xor_sync(0xffffffffu, mx, off));

    float sum = 0.0f;
#pragma unroll
    for (int t = 0; t < 8; ++t) {
        v[t].x = __expf(v[t].x - mx); v[t].y = __expf(v[t].y - mx);
        v[t].z = __expf(v[t].z - mx); v[t].w = __expf(v[t].w - mx);
        sum += v[t].x + v[t].y + v[t].z + v[t].w;
    }
#pragma unroll
    for (int off = 16; off >= 1; off >>= 1)
        sum += __shfl_xor_sync(0xffffffffu, sum, off);

    const float inv = 1.0f / sum;
#pragma unroll
    for (int t = 0; t < 8; ++t) {
        v[t].x *= inv; v[t].y *= inv; v[t].z *= inv; v[t].w *= inv;
        row[lane + t * 32] = v[t];
    }
}

// ---------------------------------------------------------------------------
// PV for Z batch-heads: O[bh][n][d] = sum_m P[z][n][m] * V[z][m][d],
// written to g_o in [B,N,C] layout. stash=1 -> V from g_v2 (device ref).
// Grid (8, Z), 128 threads. Tile 128x64, BK=16 pipelined, 8x8 micro-tile.
// ---------------------------------------------------------------------------
__global__ __launch_bounds__(128)
void pv_all(const float* __restrict__ probs_base, const float* __restrict__ vbase,
            int bh0, int stash)
{
    __shared__ float Ps[16][128];   // [kk][row] transposed
    __shared__ float Vs[16][64];

    const int tid = threadIdx.x;
    const int n0 = blockIdx.x * 128;
    const int z  = blockIdx.y;
    const int bh = bh0 + z;
    const int b  = bh / NH, h = bh % NH;

    const float* P = probs_base + (size_t)z * PSTRIDE + (size_t)n0 * NN;
    const float* V = (stash ? (const float*)g_v2 : vbase) + (size_t)z * BHD;

    const float* Pp = P + (size_t)tid * NN;          // this thread's own row
    const int vrow = tid >> 3, vq = (tid & 7) * 8;
    const float* Vp = V + (size_t)vrow * ND + vq;

    const int ty = tid >> 3, tx = tid & 7;
    const int r0 = ty * 8, c0 = tx * 8;

    float acc[8][8];
#pragma unroll
    for (int i = 0; i < 8; ++i)
#pragma unroll
        for (int j = 0; j < 8; ++j) acc[i][j] = 0.0f;

    float4 p0 = ld4(Pp), p1 = ld4(Pp + 4), p2 = ld4(Pp + 8), p3 = ld4(Pp + 12);
    float4 v0 = ld4(Vp), v1 = ld4(Vp + 4);

    for (int k0 = 0; k0 < NN; k0 += 16) {
        __syncthreads();
        Ps[ 0][tid]=p0.x; Ps[ 1][tid]=p0.y; Ps[ 2][tid]=p0.z; Ps[ 3][tid]=p0.w;
        Ps[ 4][tid]=p1.x; Ps[ 5][tid]=p1.y; Ps[ 6][tid]=p1.z; Ps[ 7][tid]=p1.w;
        Ps[ 8][tid]=p2.x; Ps[ 9][tid]=p2.y; Ps[10][tid]=p2.z; Ps[11][tid]=p2.w;
        Ps[12][tid]=p3.x; Ps[13][tid]=p3.y; Ps[14][tid]=p3.z; Ps[15][tid]=p3.w;
        *(float4*)&Vs[vrow][vq]     = v0;
        *(float4*)&Vs[vrow][vq + 4] = v1;
        __syncthreads();
        if (k0 + 16 < NN) {
            p0 = ld4(Pp + k0 + 16); p1 = ld4(Pp + k0 + 20);
            p2 = ld4(Pp + k0 + 24); p3 = ld4(Pp + k0 + 28);
            v0 = ld4(Vp + (size_t)(k0 + 16) * ND);
            v1 = ld4(Vp + (size_t)(k0 + 16) * ND + 4);
        }
#pragma unroll
        for (int kk = 0; kk < 16; ++kk) {
            __align__(16) float ar[8], br[8];
            *(float4*)&ar[0] = *(const float4*)&Ps[kk][r0];
            *(float4*)&ar[4] = *(const float4*)&Ps[kk][r0 + 4];
            *(float4*)&br[0] = *(const float4*)&Vs[kk][c0];
            *(float4*)&br[4] = *(const float4*)&Vs[kk][c0 + 4];
#pragma unroll
            for (int i = 0; i < 8; ++i)
#pragma unroll
                for (int j = 0; j < 8; ++j)
                    acc[i][j] = fmaf(ar[i], br[j], acc[i][j]);
        }
    }

#pragma unroll
    for (int i = 0; i < 8; ++i) {
        float* p = g_o + ((size_t)b * NN + n0 + r0 + i) * NC + h * ND + c0;
        *(float4*)(p)     = make_float4(acc[i][0], acc[i][1], acc[i][2], acc[i][3]);
        *(float4*)(p + 4) = make_float4(acc[i][4], acc[i][5], acc[i][6], acc[i][7]);
    }
}

// ---------------------------------------------------------------------------
// Output projection, all batches: out = g_o @ w_proj^T + bias. Grid (6, 64).
// ---------------------------------------------------------------------------
__global__ __launch_bounds__(256, 2)
void proj_all(const float* __restrict__ w, const float* __restrict__ bias,
              float* __restrict__ out)
{
    __shared__ float As[16][128];
    __shared__ float Bs[16][128];

    const int tid = threadIdx.x;
    const int m0 = blockIdx.y * 128;
    const int n0 = blockIdx.x * 128;

    const int lrow = tid >> 1;
    const int lk8  = (tid & 1) * 8;
    const float* Ap = g_o + (size_t)(m0 + lrow) * NC + lk8;
    const float* Wp = w   + (size_t)(n0 + lrow) * NC + lk8;

    const int ty = tid >> 4, tx = tid & 15;
    const int r0 = ty * 8, c0 = tx * 8;

    float acc[8][8];
#pragma unroll
    for (int i = 0; i < 8; ++i)
#pragma unroll
        for (int j = 0; j < 8; ++j) acc[i][j] = 0.0f;

    float4 a0 = ld4(Ap), a1 = ld4(Ap + 4);
    float4 b0 = ld4(Wp), b1 = ld4(Wp + 4);

    for (int k0 = 0; k0 < NC; k0 += 16) {
        __syncthreads();
        As[lk8+0][lrow]=a0.x; As[lk8+1][lrow]=a0.y; As[lk8+2][lrow]=a0.z; As[lk8+3][lrow]=a0.w;
        As[lk8+4][lrow]=a1.x; As[lk8+5][lrow]=a1.y; As[lk8+6][lrow]=a1.z; As[lk8+7][lrow]=a1.w;
        Bs[lk8+0][lrow]=b0.x; Bs[lk8+1][lrow]=b0.y; Bs[lk8+2][lrow]=b0.z; Bs[lk8+3][lrow]=b0.w;
        Bs[lk8+4][lrow]=b1.x; Bs[lk8+5][lrow]=b1.y; Bs[lk8+6][lrow]=b1.z; Bs[lk8+7][lrow]=b1.w;
        __syncthreads();
        if (k0 + 16 < NC) {
            a0 = ld4(Ap + k0 + 16); a1 = ld4(Ap + k0 + 20);
            b0 = ld4(Wp + k0 + 16); b1 = ld4(Wp + k0 + 20);
        }
#pragma unroll
        for (int kk = 0; kk < 16; ++kk) {
            __align__(16) float ar[8], br[8];
            *(float4*)&ar[0] = *(const float4*)&As[kk][r0];
            *(float4*)&ar[4] = *(const float4*)&As[kk][r0 + 4];
            *(float4*)&br[0] = *(const float4*)&Bs[kk][c0];
            *(float4*)&br[4] = *(const float4*)&Bs[kk][c0 + 4];
#pragma unroll
            for (int i = 0; i < 8; ++i)
#pragma unroll
                for (int j = 0; j < 8; ++j)
                    acc[i][j] = fmaf(ar[i], br[j], acc[i][j]);
        }
    }

    __align__(16) float bb0[8];
    *(float4*)&bb0[0] = ld4(bias + n0 + c0);
    *(float4*)&bb0[4] = ld4(bias + n0 + c0 + 4);
#pragma unroll
    for (int i = 0; i < 8; ++i) {
        float* p = out + (size_t)(m0 + r0 + i) * NC + n0 + c0;
        *(float4*)(p)     = make_float4(acc[i][0]+bb0[0], acc[i][1]+bb0[1],
                                        acc[i][2]+bb0[2], acc[i][3]+bb0[3]);
        *(float4*)(p + 4) = make_float4(acc[i][4]+bb0[4], acc[i][5]+bb0[5],
                                        acc[i][6]+bb0[6], acc[i][7]+bb0[7]);
    }
}

// ---------------------------------------------------------------------------
extern "C" void kernel_launch(void* const* d_in, const int* in_sizes, int n_in,
                              void* d_out, int out_size)
{
    // Positional per metadata order, cross-checked by unique sizes.
    const float* x      = (n_in > 0) ? (const float*)d_in[0] : nullptr;
    const float* w_qkv  = (n_in > 1) ? (const float*)d_in[1] : nullptr;
    const float* w_proj = (n_in > 2) ? (const float*)d_in[2] : nullptr;
    const float* b_proj = (n_in > 3) ? (const float*)d_in[3] : nullptr;
    for (int i = 0; i < n_in; ++i) {
        const long long s = in_sizes[i];
        if (s == 6291456LL || s == 25165824LL)      x      = (const float*)d_in[i];
        else if (s == 1769472LL || s == 7077888LL)  w_qkv  = (const float*)d_in[i];
        else if (s == 589824LL  || s == 2359296LL)  w_proj = (const float*)d_in[i];
        else if (s == 768LL     || s == 3072LL)     b_proj = (const float*)d_in[i];
    }
    if (!x || !w_qkv || !w_proj || !b_proj) return;
    if (out_size < TOTAL_ELEMS) return;

    float* out  = (float*)d_out;
    float* attn = out + OUT_ELEMS;            // [out][attn] per tuple order

    // q/k/v scratch for all 8 batches lives in the attn region tail:
    // [SCR_BASE, SCR_BASE+3*QKV_E) — only clobbered by probs of batches 6,7,
    // which are computed from the bss stash.
    float* QS = attn + SCR_BASE;
    float* KS = QS + QKV_E;
    float* VS = KS + QKV_E;

    // 1) QKV projection for all batches -> scratch in attn region
    qkv_all<<<dim3(C3 / 128, MROWS / 128), 256>>>(x, w_qkv, QS, KS, VS);

    // 2) stash q/k/v of batches 6,7 (bh 72..95) into bss
    copy67<<<1536, 256>>>((const float4*)(QS + 72 * (size_t)BHD),
                          (const float4*)(KS + 72 * (size_t)BHD),
                          (const float4*)(VS + 72 * (size_t)BHD));

    // 3) attention, batches 0..5 in one pass (z = bh = 0..71)
    score_all  <<<dim3(8, 8, 72), 256>>>(QS, KS, attn, 0);
    softmax_all<<<dim3(128, 72), 256>>>(attn);
    pv_all     <<<dim3(8, 72), 128>>>(attn, VS, 0, 0);

    // 4) attention, batches 6,7 from the bss stash (device-side symbol refs)
    float* attn67 = attn + 72 * (size_t)PSTRIDE;
    score_all  <<<dim3(8, 8, 24), 256>>>(nullptr, nullptr, attn67, 1);
    softmax_all<<<dim3(128, 24), 256>>>(attn67);
    pv_all     <<<dim3(8, 24), 128>>>(attn67, nullptr, 72, 1);

    // 5) output projection
    proj_all<<<dim3(NC / 128, MROWS / 128), 256>>>(w_proj, b_proj, out);
}

// round 10
// speedup vs baseline: 2.4758x; 1.3819x over previous
#include <cuda_runtime.h>
#include <cuda_bf16.h>
#include <cstdint>

// Problem constants
#define NB 8
#define NN 1024
#define NC 768
#define NH 12
#define ND 64
#define C3 2304
#define MROWS 8192
#define SCALE 0.125f

#define OUT_ELEMS  6291456
#define ATTN_ELEMS 100663296
#define TOTAL_ELEMS 106954752
#define BHD 65536               // NN*ND
#define PSTRIDE 1048576         // NN*NN
#define QKV_E 6291456           // NB*NH*NN*ND
#define SCR_BASE 75497472       // 72*PSTRIDE

// bss scratch: 24 + 18 = 42 MB (proven-safe size)
__device__ float g_o [(size_t)MROWS * NC];
__device__ float g_q2[2 * NH * NN * ND];
__device__ float g_k2[2 * NH * NN * ND];
__device__ float g_v2[2 * NH * NN * ND];

__device__ __forceinline__ float4 ld4(const float* p) { return *(const float4*)p; }

__device__ __forceinline__ uint32_t s2u(const void* p) {
    uint32_t a;
    asm("{ .reg .u64 t; cvta.to.shared.u64 t, %1; cvt.u32.u64 %0, t; }"
        : "=r"(a) : "l"(p));
    return a;
}

// mma.sync m16n8k16 bf16 -> fp32 (sm_80+ baseline; compiles for plain sm_103)
__device__ __forceinline__ void mma16816(float* d, const uint32_t* a,
                                         const uint32_t* b) {
    asm volatile(
        "mma.sync.aligned.m16n8k16.row.col.f32.bf16.bf16.f32 "
        "{%0,%1,%2,%3}, {%4,%5,%6,%7}, {%8,%9}, {%0,%1,%2,%3};"
        : "+f"(d[0]), "+f"(d[1]), "+f"(d[2]), "+f"(d[3])
        : "r"(a[0]), "r"(a[1]), "r"(a[2]), "r"(a[3]), "r"(b[0]), "r"(b[1]));
}
__device__ __forceinline__ void ldmx4(uint32_t* r, uint32_t addr) {
    asm volatile("ldmatrix.sync.aligned.m8n8.x4.shared.b16 {%0,%1,%2,%3}, [%4];"
                 : "=r"(r[0]), "=r"(r[1]), "=r"(r[2]), "=r"(r[3]) : "r"(addr));
}

// fp32 -> (hi, lo) bf16 split, packed as bf16x2 words
__device__ __forceinline__ void split2(float x0, float x1,
                                       uint32_t& hi, uint32_t& lo) {
    __nv_bfloat16 h0 = __float2bfloat16(x0), h1 = __float2bfloat16(x1);
    float r0 = x0 - __bfloat162float(h0);
    float r1 = x1 - __bfloat162float(h1);
    __nv_bfloat162 H = __halves2bfloat162(h0, h1);
    __nv_bfloat162 L = __halves2bfloat162(__float2bfloat16(r0),
                                          __float2bfloat16(r1));
    hi = *(uint32_t*)&H;
    lo = *(uint32_t*)&L;
}

// ---------------------------------------------------------------------------
// Tensor-core (mma.sync) GEMM: C[M,N] = A[M,768] @ W[N,768]^T, fp32 in/out,
// bf16 split-3 (AhiBhi + AloBhi + AhiBlo), fp32 accum. 128x128 CTA tile,
// BK=32, 256 threads = 8 warps (2x4), warp tile 64x32.
// MODE 0: A=x -> scatter into qs/ks/vs [bh][n][d].
// MODE 1: A=g_o (device symbol) + bias -> out.
// ---------------------------------------------------------------------------
template <int MODE>
__global__ __launch_bounds__(256, 1)
void gemm_mma(const float* __restrict__ Ain, const float* __restrict__ W,
              const float* __restrict__ bias,
              float* __restrict__ qs, float* __restrict__ ksv,
              float* __restrict__ vs, float* __restrict__ out)
{
    __shared__ __align__(16) __nv_bfloat16 Ah[128][40];   // pitch 40 -> 20-word
    __shared__ __align__(16) __nv_bfloat16 Al[128][40];   // steps: ldmatrix
    __shared__ __align__(16) __nv_bfloat16 Bh[128][40];   // conflict-free
    __shared__ __align__(16) __nv_bfloat16 Bl[128][40];

    const int tid  = threadIdx.x;
    const int lane = tid & 31, wid = tid >> 5;
    const int wm = wid >> 2, wn = wid & 3;          // 2 x 4 warp grid
    const int m0 = blockIdx.y * 128, n0 = blockIdx.x * 128;

    const float* A = (MODE == 1) ? (const float*)g_o : Ain;

    // loader mapping: thread -> (row = tid>>3 + it*32, col4 = (tid&7)*4)
    const int r_base = tid >> 3;
    const int c4     = (tid & 7) * 4;
    const float* Aptr = A + (size_t)(m0 + r_base) * NC + c4;
    const float* Wptr = W + (size_t)(n0 + r_base) * NC + c4;

    float acc[4][4][4];
#pragma unroll
    for (int mi = 0; mi < 4; ++mi)
#pragma unroll
        for (int ni = 0; ni < 4; ++ni)
#pragma unroll
            for (int q = 0; q < 4; ++q) acc[mi][ni][q] = 0.0f;

    const uint32_t uAh = s2u(Ah), uAl = s2u(Al);
    const uint32_t uBh = s2u(Bh), uBl = s2u(Bl);

    // ldmatrix lane addressing (byte offsets)
    const int arow = lane & 15;
    const int acol = (lane >> 4) * 8;
    uint32_t aoff[4];
#pragma unroll
    for (int mi = 0; mi < 4; ++mi)
        aoff[mi] = (uint32_t)(((wm * 64 + mi * 16 + arow) * 40 + acol) * 2);
    const int brow = wn * 32 + ((lane >> 4) * 8) + (lane & 7);
    const int bcol = ((lane >> 3) & 1) * 8;
    uint32_t boff[2];
#pragma unroll
    for (int g = 0; g < 2; ++g)
        boff[g] = (uint32_t)(((brow + g * 16) * 40 + bcol) * 2);

    float4 pa[4], pw[4];
#pragma unroll
    for (int it = 0; it < 4; ++it) {
        pa[it] = ld4(Aptr + (size_t)it * 32 * NC);
        pw[it] = ld4(Wptr + (size_t)it * 32 * NC);
    }

    for (int kt = 0; kt < 24; ++kt) {
        __syncthreads();                      // prev iter's ldmatrix done
#pragma unroll
        for (int it = 0; it < 4; ++it) {
            const int row = r_base + it * 32;
            uint32_t h0, l0, h1, l1;
            split2(pa[it].x, pa[it].y, h0, l0);
            split2(pa[it].z, pa[it].w, h1, l1);
            *(uint2*)&Ah[row][c4] = make_uint2(h0, h1);
            *(uint2*)&Al[row][c4] = make_uint2(l0, l1);
            split2(pw[it].x, pw[it].y, h0, l0);
            split2(pw[it].z, pw[it].w, h1, l1);
            *(uint2*)&Bh[row][c4] = make_uint2(h0, h1);
            *(uint2*)&Bl[row][c4] = make_uint2(l0, l1);
        }
        __syncthreads();
        if (kt < 23) {                        // prefetch next k-tile
#pragma unroll
            for (int it = 0; it < 4; ++it) {
                pa[it] = ld4(Aptr + (size_t)it * 32 * NC + (kt + 1) * 32);
                pw[it] = ld4(Wptr + (size_t)it * 32 * NC + (kt + 1) * 32);
            }
        }
#pragma unroll
        for (int ks = 0; ks < 2; ++ks) {      // two k16 steps per BK=32
            const uint32_t ko = (uint32_t)(ks * 32);   // 16 bf16 = 32 bytes
            uint32_t ah[4][4], al[4][4], bb[2][4];
#pragma unroll
            for (int mi = 0; mi < 4; ++mi) ldmx4(ah[mi], uAh + aoff[mi] + ko);
#pragma unroll
            for (int g = 0; g < 2; ++g) ldmx4(bb[g], uBh + boff[g] + ko);
            // phase 1: Ahi * Bhi
#pragma unroll
            for (int mi = 0; mi < 4; ++mi) {
                mma16816(acc[mi][0], ah[mi], &bb[0][0]);
                mma16816(acc[mi][1], ah[mi], &bb[0][2]);
                mma16816(acc[mi][2], ah[mi], &bb[1][0]);
                mma16816(acc[mi][3], ah[mi], &bb[1][2]);
            }
            // phase 2: Alo * Bhi
#pragma unroll
            for (int mi = 0; mi < 4; ++mi) ldmx4(al[mi], uAl + aoff[mi] + ko);
#pragma unroll
            for (int mi = 0; mi < 4; ++mi) {
                mma16816(acc[mi][0], al[mi], &bb[0][0]);
                mma16816(acc[mi][1], al[mi], &bb[0][2]);
                mma16816(acc[mi][2], al[mi], &bb[1][0]);
                mma16816(acc[mi][3], al[mi], &bb[1][2]);
            }
            // phase 3: Ahi * Blo
#pragma unroll
            for (int g = 0; g < 2; ++g) ldmx4(bb[g], uBl + boff[g] + ko);
#pragma unroll
            for (int mi = 0; mi < 4; ++mi) {
                mma16816(acc[mi][0], ah[mi], &bb[0][0]);
                mma16816(acc[mi][1], ah[mi], &bb[0][2]);
                mma16816(acc[mi][2], ah[mi], &bb[1][0]);
                mma16816(acc[mi][3], ah[mi], &bb[1][2]);
            }
        }
    }

    // Epilogue: C frag = (row erow/+8, cols ecol..ecol+1) per mma tile
    const int erow = lane >> 2;
    const int ecol = (lane & 3) * 2;
#pragma unroll
    for (int ni = 0; ni < 4; ++ni) {
        const int gc = n0 + wn * 32 + ni * 8 + ecol;
        if (MODE == 0) {
            const int s   = gc / NC;
            const int rem = gc % NC;
            const int h   = rem >> 6;
            const int d   = rem & 63;
            float* dst = (s == 0) ? qs : (s == 1) ? ksv : vs;
#pragma unroll
            for (int mi = 0; mi < 4; ++mi) {
                const int gr = m0 + wm * 64 + mi * 16 + erow;
#pragma unroll
                for (int half = 0; half < 2; ++half) {
                    const int r = gr + half * 8;
                    const int b = r >> 10, nn = r & 1023;
                    float* p = dst + (((size_t)(b * NH + h) * NN + nn) * ND + d);
                    *(float2*)p = make_float2(acc[mi][ni][half * 2],
                                              acc[mi][ni][half * 2 + 1]);
                }
            }
        } else {
            const float2 bv = *(const float2*)(bias + gc);
#pragma unroll
            for (int mi = 0; mi < 4; ++mi) {
                const int gr = m0 + wm * 64 + mi * 16 + erow;
#pragma unroll
                for (int half = 0; half < 2; ++half) {
                    float* p = out + (size_t)(gr + half * 8) * NC + gc;
                    *(float2*)p = make_float2(acc[mi][ni][half * 2] + bv.x,
                                              acc[mi][ni][half * 2 + 1] + bv.y);
                }
            }
        }
    }
}

// ---------------------------------------------------------------------------
// Stash q/k/v of batches 6,7 into bss (device-side symbol refs).
// ---------------------------------------------------------------------------
__global__ __launch_bounds__(256)
void copy67(const float4* __restrict__ qs, const float4* __restrict__ ks,
            const float4* __restrict__ vs)
{
    const int n4 = 2 * NH * NN * ND / 4;
    for (int i = blockIdx.x * blockDim.x + threadIdx.x; i < n4;
         i += gridDim.x * blockDim.x) {
        ((float4*)g_q2)[i] = qs[i];
        ((float4*)g_k2)[i] = ks[i];
        ((float4*)g_v2)[i] = vs[i];
    }
}

// ---------------------------------------------------------------------------
// Scores (SIMT, unchanged from round 8)
// ---------------------------------------------------------------------------
__global__ __launch_bounds__(256, 2)
void score_all(const float* __restrict__ qbase, const float* __restrict__ kbase,
               float* __restrict__ probs_base, int stash)
{
    __shared__ float As[16][128];
    __shared__ float Bs[16][128];

    const int tid = threadIdx.x;
    const int m0 = blockIdx.y * 128;
    const int n0 = blockIdx.x * 128;
    const int z  = blockIdx.z;

    const float* A = (stash ? (const float*)g_q2 : qbase) + (size_t)z * BHD;
    const float* W = (stash ? (const float*)g_k2 : kbase) + (size_t)z * BHD;
    float* out = probs_base + (size_t)z * PSTRIDE;

    const int lrow = tid >> 1;
    const int lk8  = (tid & 1) * 8;
    const float* Ap = A + (size_t)(m0 + lrow) * ND + lk8;
    const float* Wp = W + (size_t)(n0 + lrow) * ND + lk8;

    const int ty = tid >> 4, tx = tid & 15;
    const int r0 = ty * 8, c0 = tx * 8;

    float acc[8][8];
#pragma unroll
    for (int i = 0; i < 8; ++i)
#pragma unroll
        for (int j = 0; j < 8; ++j) acc[i][j] = 0.0f;

    float4 a0 = ld4(Ap), a1 = ld4(Ap + 4);
    float4 b0 = ld4(Wp), b1 = ld4(Wp + 4);

#pragma unroll
    for (int k0 = 0; k0 < ND; k0 += 16) {
        __syncthreads();
        As[lk8+0][lrow]=a0.x; As[lk8+1][lrow]=a0.y; As[lk8+2][lrow]=a0.z; As[lk8+3][lrow]=a0.w;
        As[lk8+4][lrow]=a1.x; As[lk8+5][lrow]=a1.y; As[lk8+6][lrow]=a1.z; As[lk8+7][lrow]=a1.w;
        Bs[lk8+0][lrow]=b0.x; Bs[lk8+1][lrow]=b0.y; Bs[lk8+2][lrow]=b0.z; Bs[lk8+3][lrow]=b0.w;
        Bs[lk8+4][lrow]=b1.x; Bs[lk8+5][lrow]=b1.y; Bs[lk8+6][lrow]=b1.z; Bs[lk8+7][lrow]=b1.w;
        __syncthreads();
        if (k0 + 16 < ND) {
            a0 = ld4(Ap + k0 + 16); a1 = ld4(Ap + k0 + 20);
            b0 = ld4(Wp + k0 + 16); b1 = ld4(Wp + k0 + 20);
        }
#pragma unroll
        for (int kk = 0; kk < 16; ++kk) {
            __align__(16) float ar[8], br[8];
            *(float4*)&ar[0] = *(const float4*)&As[kk][r0];
            *(float4*)&ar[4] = *(const float4*)&As[kk][r0 + 4];
            *(float4*)&br[0] = *(const float4*)&Bs[kk][c0];
            *(float4*)&br[4] = *(const float4*)&Bs[kk][c0 + 4];
#pragma unroll
            for (int i = 0; i < 8; ++i)
#pragma unroll
                for (int j = 0; j < 8; ++j)
                    acc[i][j] = fmaf(ar[i], br[j], acc[i][j]);
        }
    }

#pragma unroll
    for (int i = 0; i < 8; ++i) {
        float* p = out + (size_t)(m0 + r0 + i) * NN + n0 + c0;
        *(float4*)(p)     = make_float4(acc[i][0]*SCALE, acc[i][1]*SCALE,
                                        acc[i][2]*SCALE, acc[i][3]*SCALE);
        *(float4*)(p + 4) = make_float4(acc[i][4]*SCALE, acc[i][5]*SCALE,
                                        acc[i][6]*SCALE, acc[i][7]*SCALE);
    }
}

// ---------------------------------------------------------------------------
// Softmax in place (unchanged; at its DRAM roofline)
// ---------------------------------------------------------------------------
__global__ __launch_bounds__(256)
void softmax_all(float* __restrict__ probs_base)
{
    const int w    = threadIdx.x >> 5;
    const int lane = threadIdx.x & 31;
    const int z    = blockIdx.y;
    const int r    = blockIdx.x * 8 + w;

    float4* row = (float4*)(probs_base + (size_t)z * PSTRIDE + (size_t)r * NN);

    float4 v[8];
#pragma unroll
    for (int t = 0; t < 8; ++t) v[t] = row[lane + t * 32];

    float mx = -1e30f;
#pragma unroll
    for (int t = 0; t < 8; ++t)
        mx = fmaxf(mx, fmaxf(fmaxf(v[t].x, v[t].y), fmaxf(v[t].z, v[t].w)));
#pragma unroll
    for (int off = 16; off >= 1; off >>= 1)
        mx = fmaxf(mx, __shfl_xor_sync(0xffffffffu, mx, off));

    float sum = 0.0f;
#pragma unroll
    for (int t = 0; t < 8; ++t) {
        v[t].x = __expf(v[t].x - mx); v[t].y = __expf(v[t].y - mx);
        v[t].z = __expf(v[t].z - mx); v[t].w = __expf(v[t].w - mx);
        sum += v[t].x + v[t].y + v[t].z + v[t].w;
    }
#pragma unroll
    for (int off = 16; off >= 1; off >>= 1)
        sum += __shfl_xor_sync(0xffffffffu, sum, off);

    const float inv = 1.0f / sum;
#pragma unroll
    for (int t = 0; t < 8; ++t) {
        v[t].x *= inv; v[t].y *= inv; v[t].z *= inv; v[t].w *= inv;
        row[lane + t * 32] = v[t];
    }
}

// ---------------------------------------------------------------------------
// PV (SIMT, unchanged from round 8)
// ---------------------------------------------------------------------------
__global__ __launch_bounds__(128)
void pv_all(const float* __restrict__ probs_base, const float* __restrict__ vbase,
            int bh0, int stash)
{
    __shared__ float Ps[16][128];
    __shared__ float Vs[16][64];

    const int tid = threadIdx.x;
    const int n0 = blockIdx.x * 128;
    const int z  = blockIdx.y;
    const int bh = bh0 + z;
    const int b  = bh / NH, h = bh % NH;

    const float* P = probs_base + (size_t)z * PSTRIDE + (size_t)n0 * NN;
    const float* V = (stash ? (const float*)g_v2 : vbase) + (size_t)z * BHD;

    const float* Pp = P + (size_t)tid * NN;
    const int vrow = tid >> 3, vq = (tid & 7) * 8;
    const float* Vp = V + (size_t)vrow * ND + vq;

    const int ty = tid >> 3, tx = tid & 7;
    const int r0 = ty * 8, c0 = tx * 8;

    float acc[8][8];
#pragma unroll
    for (int i = 0; i < 8; ++i)
#pragma unroll
        for (int j = 0; j < 8; ++j) acc[i][j] = 0.0f;

    float4 p0 = ld4(Pp), p1 = ld4(Pp + 4), p2 = ld4(Pp + 8), p3 = ld4(Pp + 12);
    float4 v0 = ld4(Vp), v1 = ld4(Vp + 4);

    for (int k0 = 0; k0 < NN; k0 += 16) {
        __syncthreads();
        Ps[ 0][tid]=p0.x; Ps[ 1][tid]=p0.y; Ps[ 2][tid]=p0.z; Ps[ 3][tid]=p0.w;
        Ps[ 4][tid]=p1.x; Ps[ 5][tid]=p1.y; Ps[ 6][tid]=p1.z; Ps[ 7][tid]=p1.w;
        Ps[ 8][tid]=p2.x; Ps[ 9][tid]=p2.y; Ps[10][tid]=p2.z; Ps[11][tid]=p2.w;
        Ps[12][tid]=p3.x; Ps[13][tid]=p3.y; Ps[14][tid]=p3.z; Ps[15][tid]=p3.w;
        *(float4*)&Vs[vrow][vq]     = v0;
        *(float4*)&Vs[vrow][vq + 4] = v1;
        __syncthreads();
        if (k0 + 16 < NN) {
            p0 = ld4(Pp + k0 + 16); p1 = ld4(Pp + k0 + 20);
            p2 = ld4(Pp + k0 + 24); p3 = ld4(Pp + k0 + 28);
            v0 = ld4(Vp + (size_t)(k0 + 16) * ND);
            v1 = ld4(Vp + (size_t)(k0 + 16) * ND + 4);
        }
#pragma unroll
        for (int kk = 0; kk < 16; ++kk) {
            __align__(16) float ar[8], br[8];
            *(float4*)&ar[0] = *(const float4*)&Ps[kk][r0];
            *(float4*)&ar[4] = *(const float4*)&Ps[kk][r0 + 4];
            *(float4*)&br[0] = *(const float4*)&Vs[kk][c0];
            *(float4*)&br[4] = *(const float4*)&Vs[kk][c0 + 4];
#pragma unroll
            for (int i = 0; i < 8; ++i)
#pragma unroll
                for (int j = 0; j < 8; ++j)
                    acc[i][j] = fmaf(ar[i], br[j], acc[i][j]);
        }
    }

#pragma unroll
    for (int i = 0; i < 8; ++i) {
        float* p = g_o + ((size_t)b * NN + n0 + r0 + i) * NC + h * ND + c0;
        *(float4*)(p)     = make_float4(acc[i][0], acc[i][1], acc[i][2], acc[i][3]);
        *(float4*)(p + 4) = make_float4(acc[i][4], acc[i][5], acc[i][6], acc[i][7]);
    }
}

// ---------------------------------------------------------------------------
extern "C" void kernel_launch(void* const* d_in, const int* in_sizes, int n_in,
                              void* d_out, int out_size)
{
    const float* x      = (n_in > 0) ? (const float*)d_in[0] : nullptr;
    const float* w_qkv  = (n_in > 1) ? (const float*)d_in[1] : nullptr;
    const float* w_proj = (n_in > 2) ? (const float*)d_in[2] : nullptr;
    const float* b_proj = (n_in > 3) ? (const float*)d_in[3] : nullptr;
    for (int i = 0; i < n_in; ++i) {
        const long long s = in_sizes[i];
        if (s == 6291456LL || s == 25165824LL)      x      = (const float*)d_in[i];
        else if (s == 1769472LL || s == 7077888LL)  w_qkv  = (const float*)d_in[i];
        else if (s == 589824LL  || s == 2359296LL)  w_proj = (const float*)d_in[i];
        else if (s == 768LL     || s == 3072LL)     b_proj = (const float*)d_in[i];
    }
    if (!x || !w_qkv || !w_proj || !b_proj) return;
    if (out_size < TOTAL_ELEMS) return;

    float* out  = (float*)d_out;
    float* attn = out + OUT_ELEMS;

    float* QS = attn + SCR_BASE;
    float* KS = QS + QKV_E;
    float* VS = KS + QKV_E;

    // 1) QKV projection (mma.sync tensor cores) -> scratch in attn region tail
    gemm_mma<0><<<dim3(C3 / 128, MROWS / 128), 256>>>(
        x, w_qkv, nullptr, QS, KS, VS, nullptr);

    // 2) stash q/k/v of batches 6,7 into bss
    copy67<<<1536, 256>>>((const float4*)(QS + 72 * (size_t)BHD),
                          (const float4*)(KS + 72 * (size_t)BHD),
                          (const float4*)(VS + 72 * (size_t)BHD));

    // 3) attention, batches 0..5 (bh 0..71)
    score_all  <<<dim3(8, 8, 72), 256>>>(QS, KS, attn, 0);
    softmax_all<<<dim3(128, 72), 256>>>(attn);
    pv_all     <<<dim3(8, 72), 128>>>(attn, VS, 0, 0);

    // 4) attention, batches 6,7 from the bss stash
    float* attn67 = attn + 72 * (size_t)PSTRIDE;
    score_all  <<<dim3(8, 8, 24), 256>>>(nullptr, nullptr, attn67, 1);
    softmax_all<<<dim3(128, 24), 256>>>(attn67);
    pv_all     <<<dim3(8, 24), 128>>>(attn67, nullptr, 72, 1);

    // 5) output projection (mma.sync tensor cores)
    gemm_mma<1><<<dim3(NC / 128, MROWS / 128), 256>>>(
        nullptr, w_proj, b_proj, nullptr, nullptr, nullptr, out);
}

// round 11
// speedup vs baseline: 2.5038x; 1.0113x over previous
#include <cuda_runtime.h>
#include <cuda_bf16.h>
#include <cstdint>

// Problem constants
#define NB 8
#define NN 1024
#define NC 768
#define NH 12
#define ND 64
#define C3 2304
#define MROWS 8192
#define SCALE 0.125f

#define OUT_ELEMS  6291456
#define ATTN_ELEMS 100663296
#define TOTAL_ELEMS 106954752
#define BHD 65536               // NN*ND
#define PSTRIDE 1048576         // NN*NN
#define QKV_E 6291456           // NB*NH*NN*ND elements per q/k/v array
#define SCR_BASE 75497472       // 72*PSTRIDE: scratch after probs of b=0..5

// bss scratch: 24 + 18 = 42 MB (proven-safe size)
__device__ float g_o [(size_t)MROWS * NC];
__device__ float g_q2[2 * NH * NN * ND];   // holds QHi|QLo bf16 for batches 6,7
__device__ float g_k2[2 * NH * NN * ND];   // KHi|KLo
__device__ float g_v2[2 * NH * NN * ND];   // VHi|VLo

__device__ __forceinline__ float4 ld4(const float* p) { return *(const float4*)p; }

__device__ __forceinline__ uint32_t s2u(const void* p) {
    uint32_t a;
    asm("{ .reg .u64 t; cvta.to.shared.u64 t, %1; cvt.u32.u64 %0, t; }"
        : "=r"(a) : "l"(p));
    return a;
}

// mma.sync m16n8k16 bf16 -> fp32
__device__ __forceinline__ void mma16816(float* d, const uint32_t* a,
                                         const uint32_t* b) {
    asm volatile(
        "mma.sync.aligned.m16n8k16.row.col.f32.bf16.bf16.f32 "
        "{%0,%1,%2,%3}, {%4,%5,%6,%7}, {%8,%9}, {%0,%1,%2,%3};"
        : "+f"(d[0]), "+f"(d[1]), "+f"(d[2]), "+f"(d[3])
        : "r"(a[0]), "r"(a[1]), "r"(a[2]), "r"(a[3]), "r"(b[0]), "r"(b[1]));
}
__device__ __forceinline__ void ldmx4(uint32_t* r, uint32_t addr) {
    asm volatile("ldmatrix.sync.aligned.m8n8.x4.shared.b16 {%0,%1,%2,%3}, [%4];"
                 : "=r"(r[0]), "=r"(r[1]), "=r"(r[2]), "=r"(r[3]) : "r"(addr));
}
__device__ __forceinline__ void ldmx4t(uint32_t* r, uint32_t addr) {
    asm volatile("ldmatrix.sync.aligned.m8n8.x4.trans.shared.b16 {%0,%1,%2,%3}, [%4];"
                 : "=r"(r[0]), "=r"(r[1]), "=r"(r[2]), "=r"(r[3]) : "r"(addr));
}

// fp32 -> (hi, lo) bf16 split, packed as bf16x2 words
__device__ __forceinline__ void split2(float x0, float x1,
                                       uint32_t& hi, uint32_t& lo) {
    __nv_bfloat16 h0 = __float2bfloat16(x0), h1 = __float2bfloat16(x1);
    float r0 = x0 - __bfloat162float(h0);
    float r1 = x1 - __bfloat162float(h1);
    __nv_bfloat162 H = __halves2bfloat162(h0, h1);
    __nv_bfloat162 L = __halves2bfloat162(__float2bfloat16(r0),
                                          __float2bfloat16(r1));
    hi = *(uint32_t*)&H;
    lo = *(uint32_t*)&L;
}

// ---------------------------------------------------------------------------
// mma.sync GEMM: C[M,N] = A[M,768] @ W[N,768]^T, bf16 split-3, fp32 accum.
// 128x128 CTA tile, BK=32, 256 threads = 8 warps (2x4), warp tile 64x32.
// MODE 0: A=x -> q/k/v written as bf16 hi/lo pairs into scr layout
//   [QH | QL | KH | KL | VH | VL], each QKV_E bf16, [bh][n][d].
// MODE 1: A=g_o (device symbol) + bias -> fp32 out.
// ---------------------------------------------------------------------------
template <int MODE>
__global__ __launch_bounds__(256, 1)
void gemm_mma(const float* __restrict__ Ain, const float* __restrict__ W,
              const float* __restrict__ bias,
              __nv_bfloat16* __restrict__ scr, float* __restrict__ out)
{
    __shared__ __align__(16) __nv_bfloat16 Ah[128][40];
    __shared__ __align__(16) __nv_bfloat16 Al[128][40];
    __shared__ __align__(16) __nv_bfloat16 Bh[128][40];
    __shared__ __align__(16) __nv_bfloat16 Bl[128][40];

    const int tid  = threadIdx.x;
    const int lane = tid & 31, wid = tid >> 5;
    const int wm = wid >> 2, wn = wid & 3;
    const int m0 = blockIdx.y * 128, n0 = blockIdx.x * 128;

    const float* A = (MODE == 1) ? (const float*)g_o : Ain;

    const int r_base = tid >> 3;
    const int c4     = (tid & 7) * 4;
    const float* Aptr = A + (size_t)(m0 + r_base) * NC + c4;
    const float* Wptr = W + (size_t)(n0 + r_base) * NC + c4;

    float acc[4][4][4];
#pragma unroll
    for (int mi = 0; mi < 4; ++mi)
#pragma unroll
        for (int ni = 0; ni < 4; ++ni)
#pragma unroll
            for (int q = 0; q < 4; ++q) acc[mi][ni][q] = 0.0f;

    const uint32_t uAh = s2u(Ah), uAl = s2u(Al);
    const uint32_t uBh = s2u(Bh), uBl = s2u(Bl);

    const int arow = lane & 15;
    const int acol = (lane >> 4) * 8;
    uint32_t aoff[4];
#pragma unroll
    for (int mi = 0; mi < 4; ++mi)
        aoff[mi] = (uint32_t)(((wm * 64 + mi * 16 + arow) * 40 + acol) * 2);
    const int brow = wn * 32 + ((lane >> 4) * 8) + (lane & 7);
    const int bcol = ((lane >> 3) & 1) * 8;
    uint32_t boff[2];
#pragma unroll
    for (int g = 0; g < 2; ++g)
        boff[g] = (uint32_t)(((brow + g * 16) * 40 + bcol) * 2);

    float4 pa[4], pw[4];
#pragma unroll
    for (int it = 0; it < 4; ++it) {
        pa[it] = ld4(Aptr + (size_t)it * 32 * NC);
        pw[it] = ld4(Wptr + (size_t)it * 32 * NC);
    }

    for (int kt = 0; kt < 24; ++kt) {
        __syncthreads();
#pragma unroll
        for (int it = 0; it < 4; ++it) {
            const int row = r_base + it * 32;
            uint32_t h0, l0, h1, l1;
            split2(pa[it].x, pa[it].y, h0, l0);
            split2(pa[it].z, pa[it].w, h1, l1);
            *(uint2*)&Ah[row][c4] = make_uint2(h0, h1);
            *(uint2*)&Al[row][c4] = make_uint2(l0, l1);
            split2(pw[it].x, pw[it].y, h0, l0);
            split2(pw[it].z, pw[it].w, h1, l1);
            *(uint2*)&Bh[row][c4] = make_uint2(h0, h1);
            *(uint2*)&Bl[row][c4] = make_uint2(l0, l1);
        }
        __syncthreads();
        if (kt < 23) {
#pragma unroll
            for (int it = 0; it < 4; ++it) {
                pa[it] = ld4(Aptr + (size_t)it * 32 * NC + (kt + 1) * 32);
                pw[it] = ld4(Wptr + (size_t)it * 32 * NC + (kt + 1) * 32);
            }
        }
#pragma unroll
        for (int ks = 0; ks < 2; ++ks) {
            const uint32_t ko = (uint32_t)(ks * 32);
            uint32_t ah[4][4], al[4][4], bb[2][4];
#pragma unroll
            for (int mi = 0; mi < 4; ++mi) ldmx4(ah[mi], uAh + aoff[mi] + ko);
#pragma unroll
            for (int g = 0; g < 2; ++g) ldmx4(bb[g], uBh + boff[g] + ko);
#pragma unroll
            for (int mi = 0; mi < 4; ++mi) {
                mma16816(acc[mi][0], ah[mi], &bb[0][0]);
                mma16816(acc[mi][1], ah[mi], &bb[0][2]);
                mma16816(acc[mi][2], ah[mi], &bb[1][0]);
                mma16816(acc[mi][3], ah[mi], &bb[1][2]);
            }
#pragma unroll
            for (int mi = 0; mi < 4; ++mi) ldmx4(al[mi], uAl + aoff[mi] + ko);
#pragma unroll
            for (int mi = 0; mi < 4; ++mi) {
                mma16816(acc[mi][0], al[mi], &bb[0][0]);
                mma16816(acc[mi][1], al[mi], &bb[0][2]);
                mma16816(acc[mi][2], al[mi], &bb[1][0]);
                mma16816(acc[mi][3], al[mi], &bb[1][2]);
            }
#pragma unroll
            for (int g = 0; g < 2; ++g) ldmx4(bb[g], uBl + boff[g] + ko);
#pragma unroll
            for (int mi = 0; mi < 4; ++mi) {
                mma16816(acc[mi][0], ah[mi], &bb[0][0]);
                mma16816(acc[mi][1], ah[mi], &bb[0][2]);
                mma16816(acc[mi][2], ah[mi], &bb[1][0]);
                mma16816(acc[mi][3], ah[mi], &bb[1][2]);
            }
        }
    }

    const int erow = lane >> 2;
    const int ecol = (lane & 3) * 2;
#pragma unroll
    for (int ni = 0; ni < 4; ++ni) {
        const int gc = n0 + wn * 32 + ni * 8 + ecol;
        if (MODE == 0) {
            const int s   = gc / NC;
            const int rem = gc % NC;
            const int h   = rem >> 6;
            const int d   = rem & 63;
            __nv_bfloat16* dh = scr + (size_t)(2 * s) * QKV_E;
            __nv_bfloat16* dl = dh + QKV_E;
#pragma unroll
            for (int mi = 0; mi < 4; ++mi) {
                const int gr = m0 + wm * 64 + mi * 16 + erow;
#pragma unroll
                for (int half = 0; half < 2; ++half) {
                    const int r = gr + half * 8;
                    const int b = r >> 10, nn = r & 1023;
                    const size_t off = ((size_t)(b * NH + h) * NN + nn) * ND + d;
                    uint32_t hw, lw;
                    split2(acc[mi][ni][half * 2], acc[mi][ni][half * 2 + 1], hw, lw);
                    *(uint32_t*)(dh + off) = hw;
                    *(uint32_t*)(dl + off) = lw;
                }
            }
        } else {
            const float2 bv = *(const float2*)(bias + gc);
#pragma unroll
            for (int mi = 0; mi < 4; ++mi) {
                const int gr = m0 + wm * 64 + mi * 16 + erow;
#pragma unroll
                for (int half = 0; half < 2; ++half) {
                    float* p = out + (size_t)(gr + half * 8) * NC + gc;
                    *(float2*)p = make_float2(acc[mi][ni][half * 2] + bv.x,
                                              acc[mi][ni][half * 2 + 1] + bv.y);
                }
            }
        }
    }
}

// ---------------------------------------------------------------------------
// Stash bf16 q/k/v of batches 6,7 (bh 72..95) into bss.
// ---------------------------------------------------------------------------
__global__ __launch_bounds__(256)
void copy67(const __nv_bfloat16* __restrict__ scr)
{
    const int n = 24 * BHD / 8;     // uint4 per segment (196608)
    const uint4* qh = (const uint4*)(scr + 72 * (size_t)BHD);
    const uint4* ql = (const uint4*)(scr + (size_t)QKV_E + 72 * (size_t)BHD);
    const uint4* kh = (const uint4*)(scr + 2 * (size_t)QKV_E + 72 * (size_t)BHD);
    const uint4* kl = (const uint4*)(scr + 3 * (size_t)QKV_E + 72 * (size_t)BHD);
    const uint4* vh = (const uint4*)(scr + 4 * (size_t)QKV_E + 72 * (size_t)BHD);
    const uint4* vl = (const uint4*)(scr + 5 * (size_t)QKV_E + 72 * (size_t)BHD);
    uint4* dq = (uint4*)g_q2;
    uint4* dk = (uint4*)g_k2;
    uint4* dv = (uint4*)g_v2;
    for (int i = blockIdx.x * blockDim.x + threadIdx.x; i < n;
         i += gridDim.x * blockDim.x) {
        dq[i] = qh[i]; dq[n + i] = ql[i];
        dk[i] = kh[i]; dk[n + i] = kl[i];
        dv[i] = vh[i]; dv[n + i] = vl[i];
    }
}

// ---------------------------------------------------------------------------
// Scores via mma.sync: P[z][n][m] = SCALE * q[z][n][:] . k[z][m][:], split-3.
// Grid (8, 8, Z), 256 threads, 128x128 tile, K=64 as two BK=32 slabs.
// ---------------------------------------------------------------------------
__global__ __launch_bounds__(256, 1)
void score_mma(const __nv_bfloat16* __restrict__ scr,
               float* __restrict__ probs_base, int stash)
{
    __shared__ __align__(16) __nv_bfloat16 QHs[128][40], QLs[128][40];
    __shared__ __align__(16) __nv_bfloat16 KHs[128][40], KLs[128][40];

    const int tid  = threadIdx.x;
    const int lane = tid & 31, wid = tid >> 5;
    const int wm = wid >> 2, wn = wid & 3;
    const int m0 = blockIdx.y * 128, n0 = blockIdx.x * 128;
    const int z  = blockIdx.z;

    const __nv_bfloat16 *qh, *ql, *kh, *kl;
    if (stash) {
        qh = (const __nv_bfloat16*)g_q2; ql = qh + 24 * (size_t)BHD;
        kh = (const __nv_bfloat16*)g_k2; kl = kh + 24 * (size_t)BHD;
    } else {
        qh = scr;                        ql = scr + (size_t)QKV_E;
        kh = scr + 2 * (size_t)QKV_E;    kl = scr + 3 * (size_t)QKV_E;
    }
    qh += (size_t)z * BHD; ql += (size_t)z * BHD;
    kh += (size_t)z * BHD; kl += (size_t)z * BHD;

    float acc[4][4][4];
#pragma unroll
    for (int mi = 0; mi < 4; ++mi)
#pragma unroll
        for (int ni = 0; ni < 4; ++ni)
#pragma unroll
            for (int q = 0; q < 4; ++q) acc[mi][ni][q] = 0.0f;

    const uint32_t uQh = s2u(QHs), uQl = s2u(QLs);
    const uint32_t uKh = s2u(KHs), uKl = s2u(KLs);

    const int arow = lane & 15;
    const int acol = (lane >> 4) * 8;
    uint32_t aoff[4];
#pragma unroll
    for (int mi = 0; mi < 4; ++mi)
        aoff[mi] = (uint32_t)(((wm * 64 + mi * 16 + arow) * 40 + acol) * 2);
    const int brow = wn * 32 + ((lane >> 4) * 8) + (lane & 7);
    const int bcol = ((lane >> 3) & 1) * 8;
    uint32_t boff[2];
#pragma unroll
    for (int g = 0; g < 2; ++g)
        boff[g] = (uint32_t)(((brow + g * 16) * 40 + bcol) * 2);

    const int r_l = tid >> 3;
    const int c4  = (tid & 7) * 4;

#pragma unroll
    for (int kt = 0; kt < 2; ++kt) {
        __syncthreads();
#pragma unroll
        for (int it = 0; it < 4; ++it) {
            const int row = r_l + it * 32;
            const int kc = kt * 32 + c4;
            *(uint2*)&QHs[row][c4] = *(const uint2*)(qh + (size_t)(m0 + row) * ND + kc);
            *(uint2*)&QLs[row][c4] = *(const uint2*)(ql + (size_t)(m0 + row) * ND + kc);
            *(uint2*)&KHs[row][c4] = *(const uint2*)(kh + (size_t)(n0 + row) * ND + kc);
            *(uint2*)&KLs[row][c4] = *(const uint2*)(kl + (size_t)(n0 + row) * ND + kc);
        }
        __syncthreads();
#pragma unroll
        for (int ks = 0; ks < 2; ++ks) {
            const uint32_t ko = (uint32_t)(ks * 32);
            uint32_t ah[4][4], al[4][4], bb[2][4];
#pragma unroll
            for (int mi = 0; mi < 4; ++mi) ldmx4(ah[mi], uQh + aoff[mi] + ko);
#pragma unroll
            for (int g = 0; g < 2; ++g) ldmx4(bb[g], uKh + boff[g] + ko);
#pragma unroll
            for (int mi = 0; mi < 4; ++mi) {
                mma16816(acc[mi][0], ah[mi], &bb[0][0]);
                mma16816(acc[mi][1], ah[mi], &bb[0][2]);
                mma16816(acc[mi][2], ah[mi], &bb[1][0]);
                mma16816(acc[mi][3], ah[mi], &bb[1][2]);
            }
#pragma unroll
            for (int mi = 0; mi < 4; ++mi) ldmx4(al[mi], uQl + aoff[mi] + ko);
#pragma unroll
            for (int mi = 0; mi < 4; ++mi) {
                mma16816(acc[mi][0], al[mi], &bb[0][0]);
                mma16816(acc[mi][1], al[mi], &bb[0][2]);
                mma16816(acc[mi][2], al[mi], &bb[1][0]);
                mma16816(acc[mi][3], al[mi], &bb[1][2]);
            }
#pragma unroll
            for (int g = 0; g < 2; ++g) ldmx4(bb[g], uKl + boff[g] + ko);
#pragma unroll
            for (int mi = 0; mi < 4; ++mi) {
                mma16816(acc[mi][0], ah[mi], &bb[0][0]);
                mma16816(acc[mi][1], ah[mi], &bb[0][2]);
                mma16816(acc[mi][2], ah[mi], &bb[1][0]);
                mma16816(acc[mi][3], ah[mi], &bb[1][2]);
            }
        }
    }

    float* outp = probs_base + (size_t)z * PSTRIDE;
    const int erow = lane >> 2;
    const int ecol = (lane & 3) * 2;
#pragma unroll
    for (int ni = 0; ni < 4; ++ni) {
        const int gc = n0 + wn * 32 + ni * 8 + ecol;
#pragma unroll
        for (int mi = 0; mi < 4; ++mi) {
            const int gr = m0 + wm * 64 + mi * 16 + erow;
#pragma unroll
            for (int half = 0; half < 2; ++half) {
                float* p = outp + (size_t)(gr + half * 8) * NN + gc;
                *(float2*)p = make_float2(acc[mi][ni][half * 2] * SCALE,
                                          acc[mi][ni][half * 2 + 1] * SCALE);
            }
        }
    }
}

// ---------------------------------------------------------------------------
// Softmax in place (unchanged; at its DRAM roofline)
// ---------------------------------------------------------------------------
__global__ __launch_bounds__(256)
void softmax_all(float* __restrict__ probs_base)
{
    const int w    = threadIdx.x >> 5;
    const int lane = threadIdx.x & 31;
    const int z    = blockIdx.y;
    const int r    = blockIdx.x * 8 + w;

    float4* row = (float4*)(probs_base + (size_t)z * PSTRIDE + (size_t)r * NN);

    float4 v[8];
#pragma unroll
    for (int t = 0; t < 8; ++t) v[t] = row[lane + t * 32];

    float mx = -1e30f;
#pragma unroll
    for (int t = 0; t < 8; ++t)
        mx = fmaxf(mx, fmaxf(fmaxf(v[t].x, v[t].y), fmaxf(v[t].z, v[t].w)));
#pragma unroll
    for (int off = 16; off >= 1; off >>= 1)
        mx = fmaxf(mx, __shfl_xor_sync(0xffffffffu, mx, off));

    float sum = 0.0f;
#pragma unroll
    for (int t = 0; t < 8; ++t) {
        v[t].x = __expf(v[t].x - mx); v[t].y = __expf(v[t].y - mx);
        v[t].z = __expf(v[t].z - mx); v[t].w = __expf(v[t].w - mx);
        sum += v[t].x + v[t].y + v[t].z + v[t].w;
    }
#pragma unroll
    for (int off = 16; off >= 1; off >>= 1)
        sum += __shfl_xor_sync(0xffffffffu, sum, off);

    const float inv = 1.0f / sum;
#pragma unroll
    for (int t = 0; t < 8; ++t) {
        v[t].x *= inv; v[t].y *= inv; v[t].z *= inv; v[t].w *= inv;
        row[lane + t * 32] = v[t];
    }
}

// ---------------------------------------------------------------------------
// PV via mma.sync: O[bh][n][d] = sum_m P[z][n][m] * V[z][m][d], split-3.
// Grid (8, Z), 256 threads = 8 warps (4x2), warp tile 32x32. BK=32.
// A = P (fp32 -> split in loader), B = V staged [k][d], trans ldmatrix.
// ---------------------------------------------------------------------------
__global__ __launch_bounds__(256, 1)
void pv_mma(const float* __restrict__ probs_base,
            const __nv_bfloat16* __restrict__ scr, int bh0, int stash)
{
    __shared__ __align__(16) __nv_bfloat16 PH[128][40], PL[128][40];
    __shared__ __align__(16) __nv_bfloat16 VHs[32][72], VLs[32][72];

    const int tid  = threadIdx.x;
    const int lane = tid & 31, wid = tid >> 5;
    const int wm = wid >> 1, wn = wid & 1;
    const int n0 = blockIdx.x * 128;
    const int z  = blockIdx.y;
    const int bh = bh0 + z;
    const int b  = bh / NH, h = bh % NH;

    const float* P = probs_base + (size_t)z * PSTRIDE + (size_t)n0 * NN;
    const __nv_bfloat16 *vh, *vl;
    if (stash) {
        vh = (const __nv_bfloat16*)g_v2; vl = vh + 24 * (size_t)BHD;
    } else {
        vh = scr + 4 * (size_t)QKV_E;    vl = scr + 5 * (size_t)QKV_E;
    }
    vh += (size_t)z * BHD; vl += (size_t)z * BHD;

    float acc[2][4][4];
#pragma unroll
    for (int mi = 0; mi < 2; ++mi)
#pragma unroll
        for (int ni = 0; ni < 4; ++ni)
#pragma unroll
            for (int q = 0; q < 4; ++q) acc[mi][ni][q] = 0.0f;

    const uint32_t uPH = s2u(PH), uPL = s2u(PL);
    const uint32_t uVH = s2u(VHs), uVL = s2u(VLs);

    const int arow = lane & 15;
    const int acol = (lane >> 4) * 8;
    uint32_t aoff[2];
#pragma unroll
    for (int mi = 0; mi < 2; ++mi)
        aoff[mi] = (uint32_t)(((wm * 32 + mi * 16 + arow) * 40 + acol) * 2);
    // trans B: lane -> k-row (lane&7)+((lane>>3)&1)*8, n-col ((lane>>4)&1)*8
    const int tk = (lane & 7) + ((lane >> 3) & 1) * 8;
    uint32_t boff[2];
#pragma unroll
    for (int g = 0; g < 2; ++g)
        boff[g] = (uint32_t)((tk * 72 + wn * 32 + g * 16 + ((lane >> 4) & 1) * 8) * 2);

    const int pr = tid >> 3, pc4 = (tid & 7) * 4;    // P loader
    const int vr = tid >> 4, vc4 = (tid & 15) * 4;   // V loader

    float4 pa[4];
    uint2  pvh[2], pvl[2];
#pragma unroll
    for (int it = 0; it < 4; ++it)
        pa[it] = ld4(P + (size_t)(pr + it * 32) * NN + pc4);
#pragma unroll
    for (int it = 0; it < 2; ++it) {
        pvh[it] = *(const uint2*)(vh + (size_t)(vr + it * 16) * ND + vc4);
        pvl[it] = *(const uint2*)(vl + (size_t)(vr + it * 16) * ND + vc4);
    }

    for (int kt = 0; kt < 32; ++kt) {
        __syncthreads();
#pragma unroll
        for (int it = 0; it < 4; ++it) {
            const int row = pr + it * 32;
            uint32_t h0, l0, h1, l1;
            split2(pa[it].x, pa[it].y, h0, l0);
            split2(pa[it].z, pa[it].w, h1, l1);
            *(uint2*)&PH[row][pc4] = make_uint2(h0, h1);
            *(uint2*)&PL[row][pc4] = make_uint2(l0, l1);
        }
#pragma unroll
        for (int it = 0; it < 2; ++it) {
            const int row = vr + it * 16;
            *(uint2*)&VHs[row][vc4] = pvh[it];
            *(uint2*)&VLs[row][vc4] = pvl[it];
        }
        __syncthreads();
        if (kt < 31) {
#pragma unroll
            for (int it = 0; it < 4; ++it)
                pa[it] = ld4(P + (size_t)(pr + it * 32) * NN + (kt + 1) * 32 + pc4);
#pragma unroll
            for (int it = 0; it < 2; ++it) {
                const size_t vo = (size_t)((kt + 1) * 32 + vr + it * 16) * ND + vc4;
                pvh[it] = *(const uint2*)(vh + vo);
                pvl[it] = *(const uint2*)(vl + vo);
            }
        }
#pragma unroll
        for (int ks = 0; ks < 2; ++ks) {
            const uint32_t ko_a = (uint32_t)(ks * 32);
            const uint32_t ko_b = (uint32_t)(ks * 16 * 72 * 2);
            uint32_t ah[2][4], al[2][4], bb[2][4];
#pragma unroll
            for (int mi = 0; mi < 2; ++mi) ldmx4(ah[mi], uPH + aoff[mi] + ko_a);
#pragma unroll
            for (int g = 0; g < 2; ++g) ldmx4t(bb[g], uVH + boff[g] + ko_b);
#pragma unroll
            for (int mi = 0; mi < 2; ++mi) {
                mma16816(acc[mi][0], ah[mi], &bb[0][0]);
                mma16816(acc[mi][1], ah[mi], &bb[0][2]);
                mma16816(acc[mi][2], ah[mi], &bb[1][0]);
                mma16816(acc[mi][3], ah[mi], &bb[1][2]);
            }
#pragma unroll
            for (int mi = 0; mi < 2; ++mi) ldmx4(al[mi], uPL + aoff[mi] + ko_a);
#pragma unroll
            for (int mi = 0; mi < 2; ++mi) {
                mma16816(acc[mi][0], al[mi], &bb[0][0]);
                mma16816(acc[mi][1], al[mi], &bb[0][2]);
                mma16816(acc[mi][2], al[mi], &bb[1][0]);
                mma16816(acc[mi][3], al[mi], &bb[1][2]);
            }
#pragma unroll
            for (int g = 0; g < 2; ++g) ldmx4t(bb[g], uVL + boff[g] + ko_b);
#pragma unroll
            for (int mi = 0; mi < 2; ++mi) {
                mma16816(acc[mi][0], ah[mi], &bb[0][0]);
                mma16816(acc[mi][1], ah[mi], &bb[0][2]);
                mma16816(acc[mi][2], ah[mi], &bb[1][0]);
                mma16816(acc[mi][3], ah[mi], &bb[1][2]);
            }
        }
    }

    const int erow = lane >> 2;
    const int ecol = (lane & 3) * 2;
#pragma unroll
    for (int ni = 0; ni < 4; ++ni) {
        const int d = wn * 32 + ni * 8 + ecol;
#pragma unroll
        for (int mi = 0; mi < 2; ++mi) {
            const int gr = n0 + wm * 32 + mi * 16 + erow;
#pragma unroll
            for (int half = 0; half < 2; ++half) {
                float* p = g_o + ((size_t)b * NN + gr + half * 8) * NC + h * ND + d;
                *(float2*)p = make_float2(acc[mi][ni][half * 2],
                                          acc[mi][ni][half * 2 + 1]);
            }
        }
    }
}

// ---------------------------------------------------------------------------
extern "C" void kernel_launch(void* const* d_in, const int* in_sizes, int n_in,
                              void* d_out, int out_size)
{
    const float* x      = (n_in > 0) ? (const float*)d_in[0] : nullptr;
    const float* w_qkv  = (n_in > 1) ? (const float*)d_in[1] : nullptr;
    const float* w_proj = (n_in > 2) ? (const float*)d_in[2] : nullptr;
    const float* b_proj = (n_in > 3) ? (const float*)d_in[3] : nullptr;
    for (int i = 0; i < n_in; ++i) {
        const long long s = in_sizes[i];
        if (s == 6291456LL || s == 25165824LL)      x      = (const float*)d_in[i];
        else if (s == 1769472LL || s == 7077888LL)  w_qkv  = (const float*)d_in[i];
        else if (s == 589824LL  || s == 2359296LL)  w_proj = (const float*)d_in[i];
        else if (s == 768LL     || s == 3072LL)     b_proj = (const float*)d_in[i];
    }
    if (!x || !w_qkv || !w_proj || !b_proj) return;
    if (out_size < TOTAL_ELEMS) return;

    float* out  = (float*)d_out;
    float* attn = out + OUT_ELEMS;

    // bf16 q/k/v scratch in the attn region tail (same bytes as before):
    // [QH | QL | KH | KL | VH | VL], each QKV_E bf16, [bh][n][d].
    __nv_bfloat16* scr = (__nv_bfloat16*)(attn + SCR_BASE);

    // 1) QKV projection (mma.sync) -> bf16 hi/lo scratch
    gemm_mma<0><<<dim3(C3 / 128, MROWS / 128), 256>>>(
        x, w_qkv, nullptr, scr, nullptr);

    // 2) stash q/k/v of batches 6,7 into bss
    copy67<<<1536, 256>>>(scr);

    // 3) attention, batches 0..5 (bh 0..71)
    score_mma  <<<dim3(8, 8, 72), 256>>>(scr, attn, 0);
    softmax_all<<<dim3(128, 72), 256>>>(attn);
    pv_mma     <<<dim3(8, 72), 256>>>(attn, scr, 0, 0);

    // 4) attention, batches 6,7 from the bss stash
    float* attn67 = attn + 72 * (size_t)PSTRIDE;
    score_mma  <<<dim3(8, 8, 24), 256>>>(nullptr, attn67, 1);
    softmax_all<<<dim3(128, 24), 256>>>(attn67);
    pv_mma     <<<dim3(8, 24), 256>>>(attn67, nullptr, 72, 1);

    // 5) output projection (mma.sync)
    gemm_mma<1><<<dim3(NC / 128, MROWS / 128), 256>>>(
        nullptr, w_proj, b_proj, nullptr, out);
}

// round 13
// speedup vs baseline: 3.6549x; 1.4598x over previous
#include <cuda_runtime.h>
#include <cuda_bf16.h>
#include <cstdint>

// Problem constants
#define NB 8
#define NN 1024
#define NC 768
#define NH 12
#define ND 64
#define C3 2304
#define MROWS 8192
#define SCALE 0.125f

#define OUT_ELEMS  6291456
#define ATTN_ELEMS 100663296
#define TOTAL_ELEMS 106954752
#define BHD 65536               // NN*ND
#define PSTRIDE 1048576         // NN*NN
#define QKV_E 6291456           // NB*NH*NN*ND elements per q/k/v array
#define SCR_BASE 75497472       // 72*PSTRIDE

// bss: O hi/lo 25MB + stash 19MB + weights 9.5MB ~ 53MB
__device__ __nv_bfloat16 g_oh[(size_t)MROWS * NC];
__device__ __nv_bfloat16 g_ol[(size_t)MROWS * NC];
__device__ __nv_bfloat16 g_wqh[(size_t)C3 * NC];
__device__ __nv_bfloat16 g_wql[(size_t)C3 * NC];
__device__ __nv_bfloat16 g_wph[(size_t)NC * NC];
__device__ __nv_bfloat16 g_wpl[(size_t)NC * NC];
__device__ float g_q2[2 * NH * NN * ND];   // QHi|QLo bf16 stash, batches 6,7
__device__ float g_k2[2 * NH * NN * ND];
__device__ float g_v2[2 * NH * NN * ND];

__device__ __forceinline__ float4 ld4(const float* p) { return *(const float4*)p; }

__device__ __forceinline__ uint32_t s2u(const void* p) {
    uint32_t a;
    asm("{ .reg .u64 t; cvta.to.shared.u64 t, %1; cvt.u32.u64 %0, t; }"
        : "=r"(a) : "l"(p));
    return a;
}

__device__ __forceinline__ void mma16816(float* d, const uint32_t* a,
                                         const uint32_t* b) {
    asm volatile(
        "mma.sync.aligned.m16n8k16.row.col.f32.bf16.bf16.f32 "
        "{%0,%1,%2,%3}, {%4,%5,%6,%7}, {%8,%9}, {%0,%1,%2,%3};"
        : "+f"(d[0]), "+f"(d[1]), "+f"(d[2]), "+f"(d[3])
        : "r"(a[0]), "r"(a[1]), "r"(a[2]), "r"(a[3]), "r"(b[0]), "r"(b[1]));
}
__device__ __forceinline__ void ldmx4(uint32_t* r, uint32_t addr) {
    asm volatile("ldmatrix.sync.aligned.m8n8.x4.shared.b16 {%0,%1,%2,%3}, [%4];"
                 : "=r"(r[0]), "=r"(r[1]), "=r"(r[2]), "=r"(r[3]) : "r"(addr));
}
__device__ __forceinline__ void ldmx4t(uint32_t* r, uint32_t addr) {
    asm volatile("ldmatrix.sync.aligned.m8n8.x4.trans.shared.b16 {%0,%1,%2,%3}, [%4];"
                 : "=r"(r[0]), "=r"(r[1]), "=r"(r[2]), "=r"(r[3]) : "r"(addr));
}

// Fast Dekker split: hi = bf16-truncate(x) (exact residual), lo = rn(x - hi).
// Error of hi+lo vs x: <= 2^-17 relative. ~6 instr per 2 elements.
__device__ __forceinline__ void split2(float x0, float x1,
                                       uint32_t& hi, uint32_t& lo) {
    const uint32_t u0 = __float_as_uint(x0), u1 = __float_as_uint(x1);
    hi = __byte_perm(u0, u1, 0x7632);             // {x0.hi16, x1.hi16}
    const float h0f = __uint_as_float(u0 & 0xFFFF0000u);
    const float h1f = __uint_as_float(u1 & 0xFFFF0000u);
    const float l0 = x0 - h0f, l1 = x1 - h1f;     // exact
    asm("cvt.rn.bf16x2.f32 %0, %1, %2;" : "=r"(lo) : "f"(l1), "f"(l0));
}

// ---------------------------------------------------------------------------
// Split-convert fp32 array -> bf16 hi/lo arrays. dst_sel: 0=args, 1=w_qkv bss,
// 2=w_proj bss (device-side symbol resolution).
// ---------------------------------------------------------------------------
__global__ __launch_bounds__(256)
void cvt_split(const float* __restrict__ src, __nv_bfloat16* hi_arg,
               __nv_bfloat16* lo_arg, int dst_sel, int n4)
{
    __nv_bfloat16* hi = hi_arg;
    __nv_bfloat16* lo = lo_arg;
    if (dst_sel == 1) { hi = g_wqh; lo = g_wql; }
    else if (dst_sel == 2) { hi = g_wph; lo = g_wpl; }
    const int i = blockIdx.x * blockDim.x + threadIdx.x;
    if (i < n4) {
        const float4 v = ((const float4*)src)[i];
        uint32_t h0, l0, h1, l1;
        split2(v.x, v.y, h0, l0);
        split2(v.z, v.w, h1, l1);
        ((uint2*)hi)[i] = make_uint2(h0, h1);
        ((uint2*)lo)[i] = make_uint2(l0, l1);
    }
}

// ---------------------------------------------------------------------------
// mma.sync GEMM on pre-split bf16 operands: C = A @ W^T, split-3, fp32 accum.
// 128x128 CTA tile, BK=32, 256 threads = 8 warps (2x4), warp tile 64x32.
// MODE 0: A = x hi/lo (args), W = g_wqh/l -> q/k/v bf16 hi/lo scratch.
// MODE 1: A = g_oh/l, W = g_wph/l (+bias) -> fp32 out.
// ---------------------------------------------------------------------------
template <int MODE>
__global__ __launch_bounds__(256, 1)
void gemm_mma(const __nv_bfloat16* __restrict__ xhi,
              const __nv_bfloat16* __restrict__ xlo,
              const float* __restrict__ bias,
              __nv_bfloat16* __restrict__ scr, float* __restrict__ out)
{
    __shared__ __align__(16) __nv_bfloat16 Ah[128][40];
    __shared__ __align__(16) __nv_bfloat16 Al[128][40];
    __shared__ __align__(16) __nv_bfloat16 Bh[128][40];
    __shared__ __align__(16) __nv_bfloat16 Bl[128][40];

    const int tid  = threadIdx.x;
    const int lane = tid & 31, wid = tid >> 5;
    const int wm = wid >> 2, wn = wid & 3;
    const int m0 = blockIdx.y * 128, n0 = blockIdx.x * 128;

    const __nv_bfloat16 *Ahi, *Alo, *Whi, *Wlo;
    if (MODE == 0) { Ahi = xhi;  Alo = xlo;  Whi = g_wqh; Wlo = g_wql; }
    else           { Ahi = g_oh; Alo = g_ol; Whi = g_wph; Wlo = g_wpl; }

    const int r_base = tid >> 3;          // 0..31
    const int c4     = (tid & 7) * 4;     // 0..28
    const __nv_bfloat16* Aph = Ahi + (size_t)(m0 + r_base) * NC + c4;
    const __nv_bfloat16* Apl = Alo + (size_t)(m0 + r_base) * NC + c4;
    const __nv_bfloat16* Wph = Whi + (size_t)(n0 + r_base) * NC + c4;
    const __nv_bfloat16* Wpl = Wlo + (size_t)(n0 + r_base) * NC + c4;

    float acc[4][4][4];
#pragma unroll
    for (int mi = 0; mi < 4; ++mi)
#pragma unroll
        for (int ni = 0; ni < 4; ++ni)
#pragma unroll
            for (int q = 0; q < 4; ++q) acc[mi][ni][q] = 0.0f;

    const uint32_t uAh = s2u(Ah), uAl = s2u(Al);
    const uint32_t uBh = s2u(Bh), uBl = s2u(Bl);

    const int arow = lane & 15;
    const int acol = (lane >> 4) * 8;
    uint32_t aoff[4];
#pragma unroll
    for (int mi = 0; mi < 4; ++mi)
        aoff[mi] = (uint32_t)(((wm * 64 + mi * 16 + arow) * 40 + acol) * 2);
    const int brow = wn * 32 + ((lane >> 4) * 8) + (lane & 7);
    const int bcol = ((lane >> 3) & 1) * 8;
    uint32_t boff[2];
#pragma unroll
    for (int g = 0; g < 2; ++g)
        boff[g] = (uint32_t)(((brow + g * 16) * 40 + bcol) * 2);

    uint2 pah[4], pal[4], pwh[4], pwl[4];
#pragma unroll
    for (int it = 0; it < 4; ++it) {
        const size_t o = (size_t)it * 32 * NC;
        pah[it] = *(const uint2*)(Aph + o);
        pal[it] = *(const uint2*)(Apl + o);
        pwh[it] = *(const uint2*)(Wph + o);
        pwl[it] = *(const uint2*)(Wpl + o);
    }

    for (int kt = 0; kt < 24; ++kt) {
        __syncthreads();
#pragma unroll
        for (int it = 0; it < 4; ++it) {
            const int row = r_base + it * 32;
            *(uint2*)&Ah[row][c4] = pah[it];
            *(uint2*)&Al[row][c4] = pal[it];
            *(uint2*)&Bh[row][c4] = pwh[it];
            *(uint2*)&Bl[row][c4] = pwl[it];
        }
        __syncthreads();
        if (kt < 23) {
#pragma unroll
            for (int it = 0; it < 4; ++it) {
                const size_t o = (size_t)it * 32 * NC + (kt + 1) * 32;
                pah[it] = *(const uint2*)(Aph + o);
                pal[it] = *(const uint2*)(Apl + o);
                pwh[it] = *(const uint2*)(Wph + o);
                pwl[it] = *(const uint2*)(Wpl + o);
            }
        }
#pragma unroll
        for (int ks = 0; ks < 2; ++ks) {
            const uint32_t ko = (uint32_t)(ks * 32);
            uint32_t ah[4][4], al[4][4], bb[2][4];
#pragma unroll
            for (int mi = 0; mi < 4; ++mi) ldmx4(ah[mi], uAh + aoff[mi] + ko);
#pragma unroll
            for (int g = 0; g < 2; ++g) ldmx4(bb[g], uBh + boff[g] + ko);
#pragma unroll
            for (int mi = 0; mi < 4; ++mi) {
                mma16816(acc[mi][0], ah[mi], &bb[0][0]);
                mma16816(acc[mi][1], ah[mi], &bb[0][2]);
                mma16816(acc[mi][2], ah[mi], &bb[1][0]);
                mma16816(acc[mi][3], ah[mi], &bb[1][2]);
            }
#pragma unroll
            for (int mi = 0; mi < 4; ++mi) ldmx4(al[mi], uAl + aoff[mi] + ko);
#pragma unroll
            for (int mi = 0; mi < 4; ++mi) {
                mma16816(acc[mi][0], al[mi], &bb[0][0]);
                mma16816(acc[mi][1], al[mi], &bb[0][2]);
                mma16816(acc[mi][2], al[mi], &bb[1][0]);
                mma16816(acc[mi][3], al[mi], &bb[1][2]);
            }
#pragma unroll
            for (int g = 0; g < 2; ++g) ldmx4(bb[g], uBl + boff[g] + ko);
#pragma unroll
            for (int mi = 0; mi < 4; ++mi) {
                mma16816(acc[mi][0], ah[mi], &bb[0][0]);
                mma16816(acc[mi][1], ah[mi], &bb[0][2]);
                mma16816(acc[mi][2], ah[mi], &bb[1][0]);
                mma16816(acc[mi][3], ah[mi], &bb[1][2]);
            }
        }
    }

    const int erow = lane >> 2;
    const int ecol = (lane & 3) * 2;
#pragma unroll
    for (int ni = 0; ni < 4; ++ni) {
        const int gc = n0 + wn * 32 + ni * 8 + ecol;
        if (MODE == 0) {
            const int s   = gc / NC;
            const int rem = gc % NC;
            const int h   = rem >> 6;
            const int d   = rem & 63;
            __nv_bfloat16* dh = scr + (size_t)(2 * s) * QKV_E;
            __nv_bfloat16* dl = dh + QKV_E;
#pragma unroll
            for (int mi = 0; mi < 4; ++mi) {
                const int gr = m0 + wm * 64 + mi * 16 + erow;
#pragma unroll
                for (int half = 0; half < 2; ++half) {
                    const int r = gr + half * 8;
                    const int b = r >> 10, nn = r & 1023;
                    const size_t off = ((size_t)(b * NH + h) * NN + nn) * ND + d;
                    uint32_t hw, lw;
                    split2(acc[mi][ni][half * 2], acc[mi][ni][half * 2 + 1], hw, lw);
                    *(uint32_t*)(dh + off) = hw;
                    *(uint32_t*)(dl + off) = lw;
                }
            }
        } else {
            const float2 bv = *(const float2*)(bias + gc);
#pragma unroll
            for (int mi = 0; mi < 4; ++mi) {
                const int gr = m0 + wm * 64 + mi * 16 + erow;
#pragma unroll
                for (int half = 0; half < 2; ++half) {
                    float* p = out + (size_t)(gr + half * 8) * NC + gc;
                    *(float2*)p = make_float2(acc[mi][ni][half * 2] + bv.x,
                                              acc[mi][ni][half * 2 + 1] + bv.y);
                }
            }
        }
    }
}

// ---------------------------------------------------------------------------
// Stash bf16 q/k/v of batches 6,7 (bh 72..95) into bss.
// ---------------------------------------------------------------------------
__global__ __launch_bounds__(256)
void copy67(const __nv_bfloat16* __restrict__ scr)
{
    const int n = 24 * BHD / 8;     // uint4 per segment
    const uint4* qh = (const uint4*)(scr + 72 * (size_t)BHD);
    const uint4* ql = (const uint4*)(scr + (size_t)QKV_E + 72 * (size_t)BHD);
    const uint4* kh = (const uint4*)(scr + 2 * (size_t)QKV_E + 72 * (size_t)BHD);
    const uint4* kl = (const uint4*)(scr + 3 * (size_t)QKV_E + 72 * (size_t)BHD);
    const uint4* vh = (const uint4*)(scr + 4 * (size_t)QKV_E + 72 * (size_t)BHD);
    const uint4* vl = (const uint4*)(scr + 5 * (size_t)QKV_E + 72 * (size_t)BHD);
    uint4* dq = (uint4*)g_q2;
    uint4* dk = (uint4*)g_k2;
    uint4* dv = (uint4*)g_v2;
    for (int i = blockIdx.x * blockDim.x + threadIdx.x; i < n;
         i += gridDim.x * blockDim.x) {
        dq[i] = qh[i]; dq[n + i] = ql[i];
        dk[i] = kh[i]; dk[n + i] = kl[i];
        dv[i] = vh[i]; dv[n + i] = vl[i];
    }
}

// ---------------------------------------------------------------------------
// Scores via mma.sync: P = SCALE * q . k^T, split-3, pre-split bf16 inputs.
// ---------------------------------------------------------------------------
__global__ __launch_bounds__(256, 1)
void score_mma(const __nv_bfloat16* __restrict__ scr,
               float* __restrict__ probs_base, int stash)
{
    __shared__ __align__(16) __nv_bfloat16 QHs[128][40], QLs[128][40];
    __shared__ __align__(16) __nv_bfloat16 KHs[128][40], KLs[128][40];

    const int tid  = threadIdx.x;
    const int lane = tid & 31, wid = tid >> 5;
    const int wm = wid >> 2, wn = wid & 3;
    const int m0 = blockIdx.y * 128, n0 = blockIdx.x * 128;
    const int z  = blockIdx.z;

    const __nv_bfloat16 *qh, *ql, *kh, *kl;
    if (stash) {
        qh = (const __nv_bfloat16*)g_q2; ql = qh + 24 * (size_t)BHD;
        kh = (const __nv_bfloat16*)g_k2; kl = kh + 24 * (size_t)BHD;
    } else {
        qh = scr;                        ql = scr + (size_t)QKV_E;
        kh = scr + 2 * (size_t)QKV_E;    kl = scr + 3 * (size_t)QKV_E;
    }
    qh += (size_t)z * BHD; ql += (size_t)z * BHD;
    kh += (size_t)z * BHD; kl += (size_t)z * BHD;

    float acc[4][4][4];
#pragma unroll
    for (int mi = 0; mi < 4; ++mi)
#pragma unroll
        for (int ni = 0; ni < 4; ++ni)
#pragma unroll
            for (int q = 0; q < 4; ++q) acc[mi][ni][q] = 0.0f;

    const uint32_t uQh = s2u(QHs), uQl = s2u(QLs);
    const uint32_t uKh = s2u(KHs), uKl = s2u(KLs);

    const int arow = lane & 15;
    const int acol = (lane >> 4) * 8;
    uint32_t aoff[4];
#pragma unroll
    for (int mi = 0; mi < 4; ++mi)
        aoff[mi] = (uint32_t)(((wm * 64 + mi * 16 + arow) * 40 + acol) * 2);
    const int brow = wn * 32 + ((lane >> 4) * 8) + (lane & 7);
    const int bcol = ((lane >> 3) & 1) * 8;
    uint32_t boff[2];
#pragma unroll
    for (int g = 0; g < 2; ++g)
        boff[g] = (uint32_t)(((brow + g * 16) * 40 + bcol) * 2);

    const int r_l = tid >> 3;
    const int c4  = (tid & 7) * 4;

#pragma unroll
    for (int kt = 0; kt < 2; ++kt) {
        __syncthreads();
#pragma unroll
        for (int it = 0; it < 4; ++it) {
            const int row = r_l + it * 32;
            const int kc = kt * 32 + c4;
            *(uint2*)&QHs[row][c4] = *(const uint2*)(qh + (size_t)(m0 + row) * ND + kc);
            *(uint2*)&QLs[row][c4] = *(const uint2*)(ql + (size_t)(m0 + row) * ND + kc);
            *(uint2*)&KHs[row][c4] = *(const uint2*)(kh + (size_t)(n0 + row) * ND + kc);
            *(uint2*)&KLs[row][c4] = *(const uint2*)(kl + (size_t)(n0 + row) * ND + kc);
        }
        __syncthreads();
#pragma unroll
        for (int ks = 0; ks < 2; ++ks) {
            const uint32_t ko = (uint32_t)(ks * 32);
            uint32_t ah[4][4], al[4][4], bb[2][4];
#pragma unroll
            for (int mi = 0; mi < 4; ++mi) ldmx4(ah[mi], uQh + aoff[mi] + ko);
#pragma unroll
            for (int g = 0; g < 2; ++g) ldmx4(bb[g], uKh + boff[g] + ko);
#pragma unroll
            for (int mi = 0; mi < 4; ++mi) {
                mma16816(acc[mi][0], ah[mi], &bb[0][0]);
                mma16816(acc[mi][1], ah[mi], &bb[0][2]);
                mma16816(acc[mi][2], ah[mi], &bb[1][0]);
                mma16816(acc[mi][3], ah[mi], &bb[1][2]);
            }
#pragma unroll
            for (int mi = 0; mi < 4; ++mi) ldmx4(al[mi], uQl + aoff[mi] + ko);
#pragma unroll
            for (int mi = 0; mi < 4; ++mi) {
                mma16816(acc[mi][0], al[mi], &bb[0][0]);
                mma16816(acc[mi][1], al[mi], &bb[0][2]);
                mma16816(acc[mi][2], al[mi], &bb[1][0]);
                mma16816(acc[mi][3], al[mi], &bb[1][2]);
            }
#pragma unroll
            for (int g = 0; g < 2; ++g) ldmx4(bb[g], uKl + boff[g] + ko);
#pragma unroll
            for (int mi = 0; mi < 4; ++mi) {
                mma16816(acc[mi][0], ah[mi], &bb[0][0]);
                mma16816(acc[mi][1], ah[mi], &bb[0][2]);
                mma16816(acc[mi][2], ah[mi], &bb[1][0]);
                mma16816(acc[mi][3], ah[mi], &bb[1][2]);
            }
        }
    }

    float* outp = probs_base + (size_t)z * PSTRIDE;
    const int erow = lane >> 2;
    const int ecol = (lane & 3) * 2;
#pragma unroll
    for (int ni = 0; ni < 4; ++ni) {
        const int gc = n0 + wn * 32 + ni * 8 + ecol;
#pragma unroll
        for (int mi = 0; mi < 4; ++mi) {
            const int gr = m0 + wm * 64 + mi * 16 + erow;
#pragma unroll
            for (int half = 0; half < 2; ++half) {
                float* p = outp + (size_t)(gr + half * 8) * NN + gc;
                *(float2*)p = make_float2(acc[mi][ni][half * 2] * SCALE,
                                          acc[mi][ni][half * 2 + 1] * SCALE);
            }
        }
    }
}

// ---------------------------------------------------------------------------
// Softmax in place (at its DRAM roofline)
// ---------------------------------------------------------------------------
__global__ __launch_bounds__(256)
void softmax_all(float* __restrict__ probs_base)
{
    const int w    = threadIdx.x >> 5;
    const int lane = threadIdx.x & 31;
    const int z    = blockIdx.y;
    const int r    = blockIdx.x * 8 + w;

    float4* row = (float4*)(probs_base + (size_t)z * PSTRIDE + (size_t)r * NN);

    float4 v[8];
#pragma unroll
    for (int t = 0; t < 8; ++t) v[t] = row[lane + t * 32];

    float mx = -1e30f;
#pragma unroll
    for (int t = 0; t < 8; ++t)
        mx = fmaxf(mx, fmaxf(fmaxf(v[t].x, v[t].y), fmaxf(v[t].z, v[t].w)));
#pragma unroll
    for (int off = 16; off >= 1; off >>= 1)
        mx = fmaxf(mx, __shfl_xor_sync(0xffffffffu, mx, off));

    float sum = 0.0f;
#pragma unroll
    for (int t = 0; t < 8; ++t) {
        v[t].x = __expf(v[t].x - mx); v[t].y = __expf(v[t].y - mx);
        v[t].z = __expf(v[t].z - mx); v[t].w = __expf(v[t].w - mx);
        sum += v[t].x + v[t].y + v[t].z + v[t].w;
    }
#pragma unroll
    for (int off = 16; off >= 1; off >>= 1)
        sum += __shfl_xor_sync(0xffffffffu, sum, off);

    const float inv = 1.0f / sum;
#pragma unroll
    for (int t = 0; t < 8; ++t) {
        v[t].x *= inv; v[t].y *= inv; v[t].z *= inv; v[t].w *= inv;
        row[lane + t * 32] = v[t];
    }
}

// ---------------------------------------------------------------------------
// PV via mma.sync: O = P @ V, split-3; O written as bf16 hi/lo (g_oh/g_ol).
// Grid (8, Z), 256 threads = 8 warps (4x2), warp tile 32x32, BK=32.
// ---------------------------------------------------------------------------
__global__ __launch_bounds__(256, 1)
void pv_mma(const float* __restrict__ probs_base,
            const __nv_bfloat16* __restrict__ scr, int bh0, int stash)
{
    __shared__ __align__(16) __nv_bfloat16 PH[128][40], PL[128][40];
    __shared__ __align__(16) __nv_bfloat16 VHs[32][72], VLs[32][72];

    const int tid  = threadIdx.x;
    const int lane = tid & 31, wid = tid >> 5;
    const int wm = wid >> 1, wn = wid & 1;
    const int n0 = blockIdx.x * 128;
    const int z  = blockIdx.y;
    const int bh = bh0 + z;
    const int b  = bh / NH, h = bh % NH;

    const float* P = probs_base + (size_t)z * PSTRIDE + (size_t)n0 * NN;
    const __nv_bfloat16 *vh, *vl;
    if (stash) {
        vh = (const __nv_bfloat16*)g_v2; vl = vh + 24 * (size_t)BHD;
    } else {
        vh = scr + 4 * (size_t)QKV_E;    vl = scr + 5 * (size_t)QKV_E;
    }
    vh += (size_t)z * BHD; vl += (size_t)z * BHD;

    float acc[2][4][4];
#pragma unroll
    for (int mi = 0; mi < 2; ++mi)
#pragma unroll
        for (int ni = 0; ni < 4; ++ni)
#pragma unroll
            for (int q = 0; q < 4; ++q) acc[mi][ni][q] = 0.0f;

    const uint32_t uPH = s2u(PH), uPL = s2u(PL);
    const uint32_t uVH = s2u(VHs), uVL = s2u(VLs);

    const int arow = lane & 15;
    const int acol = (lane >> 4) * 8;
    uint32_t aoff[2];
#pragma unroll
    for (int mi = 0; mi < 2; ++mi)
        aoff[mi] = (uint32_t)(((wm * 32 + mi * 16 + arow) * 40 + acol) * 2);
    const int tk = (lane & 7) + ((lane >> 3) & 1) * 8;
    uint32_t boff[2];
#pragma unroll
    for (int g = 0; g < 2; ++g)
        boff[g] = (uint32_t)((tk * 72 + wn * 32 + g * 16 + ((lane >> 4) & 1) * 8) * 2);

    const int pr = tid >> 3, pc4 = (tid & 7) * 4;
    const int vr = tid >> 4, vc4 = (tid & 15) * 4;

    float4 pa[4];
    uint2  pvh[2], pvl[2];
#pragma unroll
    for (int it = 0; it < 4; ++it)
        pa[it] = ld4(P + (size_t)(pr + it * 32) * NN + pc4);
#pragma unroll
    for (int it = 0; it < 2; ++it) {
        pvh[it] = *(const uint2*)(vh + (size_t)(vr + it * 16) * ND + vc4);
        pvl[it] = *(const uint2*)(vl + (size_t)(vr + it * 16) * ND + vc4);
    }

    for (int kt = 0; kt < 32; ++kt) {
        __syncthreads();
#pragma unroll
        for (int it = 0; it < 4; ++it) {
            const int row = pr + it * 32;
            uint32_t h0, l0, h1, l1;
            split2(pa[it].x, pa[it].y, h0, l0);
            split2(pa[it].z, pa[it].w, h1, l1);
            *(uint2*)&PH[row][pc4] = make_uint2(h0, h1);
            *(uint2*)&PL[row][pc4] = make_uint2(l0, l1);
        }
#pragma unroll
        for (int it = 0; it < 2; ++it) {
            const int row = vr + it * 16;
            *(uint2*)&VHs[row][vc4] = pvh[it];
            *(uint2*)&VLs[row][vc4] = pvl[it];
        }
        __syncthreads();
        if (kt < 31) {
#pragma unroll
            for (int it = 0; it < 4; ++it)
                pa[it] = ld4(P + (size_t)(pr + it * 32) * NN + (kt + 1) * 32 + pc4);
#pragma unroll
            for (int it = 0; it < 2; ++it) {
                const size_t vo = (size_t)((kt + 1) * 32 + vr + it * 16) * ND + vc4;
                pvh[it] = *(const uint2*)(vh + vo);
                pvl[it] = *(const uint2*)(vl + vo);
            }
        }
#pragma unroll
        for (int ks = 0; ks < 2; ++ks) {
            const uint32_t ko_a = (uint32_t)(ks * 32);
            const uint32_t ko_b = (uint32_t)(ks * 16 * 72 * 2);
            uint32_t ah[2][4], al[2][4], bb[2][4];
#pragma unroll
            for (int mi = 0; mi < 2; ++mi) ldmx4(ah[mi], uPH + aoff[mi] + ko_a);
#pragma unroll
            for (int g = 0; g < 2; ++g) ldmx4t(bb[g], uVH + boff[g] + ko_b);
#pragma unroll
            for (int mi = 0; mi < 2; ++mi) {
                mma16816(acc[mi][0], ah[mi], &bb[0][0]);
                mma16816(acc[mi][1], ah[mi], &bb[0][2]);
                mma16816(acc[mi][2], ah[mi], &bb[1][0]);
                mma16816(acc[mi][3], ah[mi], &bb[1][2]);
            }
#pragma unroll
            for (int mi = 0; mi < 2; ++mi) ldmx4(al[mi], uPL + aoff[mi] + ko_a);
#pragma unroll
            for (int mi = 0; mi < 2; ++mi) {
                mma16816(acc[mi][0], al[mi], &bb[0][0]);
                mma16816(acc[mi][1], al[mi], &bb[0][2]);
                mma16816(acc[mi][2], al[mi], &bb[1][0]);
                mma16816(acc[mi][3], al[mi], &bb[1][2]);
            }
#pragma unroll
            for (int g = 0; g < 2; ++g) ldmx4t(bb[g], uVL + boff[g] + ko_b);
#pragma unroll
            for (int mi = 0; mi < 2; ++mi) {
                mma16816(acc[mi][0], ah[mi], &bb[0][0]);
                mma16816(acc[mi][1], ah[mi], &bb[0][2]);
                mma16816(acc[mi][2], ah[mi], &bb[1][0]);
                mma16816(acc[mi][3], ah[mi], &bb[1][2]);
            }
        }
    }

    const int erow = lane >> 2;
    const int ecol = (lane & 3) * 2;
#pragma unroll
    for (int ni = 0; ni < 4; ++ni) {
        const int d = wn * 32 + ni * 8 + ecol;
#pragma unroll
        for (int mi = 0; mi < 2; ++mi) {
            const int gr = n0 + wm * 32 + mi * 16 + erow;
#pragma unroll
            for (int half = 0; half < 2; ++half) {
                const size_t off = ((size_t)b * NN + gr + half * 8) * NC + h * ND + d;
                uint32_t hw, lw;
                split2(acc[mi][ni][half * 2], acc[mi][ni][half * 2 + 1], hw, lw);
                *(uint32_t*)(g_oh + off) = hw;
                *(uint32_t*)(g_ol + off) = lw;
            }
        }
    }
}

// ---------------------------------------------------------------------------
extern "C" void kernel_launch(void* const* d_in, const int* in_sizes, int n_in,
                              void* d_out, int out_size)
{
    const float* x      = (n_in > 0) ? (const float*)d_in[0] : nullptr;
    const float* w_qkv  = (n_in > 1) ? (const float*)d_in[1] : nullptr;
    const float* w_proj = (n_in > 2) ? (const float*)d_in[2] : nullptr;
    const float* b_proj = (n_in > 3) ? (const float*)d_in[3] : nullptr;
    for (int i = 0; i < n_in; ++i) {
        const long long s = in_sizes[i];
        if (s == 6291456LL || s == 25165824LL)      x      = (const float*)d_in[i];
        else if (s == 1769472LL || s == 7077888LL)  w_qkv  = (const float*)d_in[i];
        else if (s == 589824LL  || s == 2359296LL)  w_proj = (const float*)d_in[i];
        else if (s == 768LL     || s == 3072LL)     b_proj = (const float*)d_in[i];
    }
    if (!x || !w_qkv || !w_proj || !b_proj) return;
    if (out_size < TOTAL_ELEMS) return;

    float* out  = (float*)d_out;
    float* attn = out + OUT_ELEMS;

    // attn-region tail: [QH|QL|KH|KL|VH|VL] bf16 scratch, then x hi/lo bf16.
    // All of it is clobbered only by batch-6/7 probs (step 4), after last use.
    __nv_bfloat16* scr = (__nv_bfloat16*)(attn + SCR_BASE);
    __nv_bfloat16* xhi = scr + 6 * (size_t)QKV_E;
    __nv_bfloat16* xlo = xhi + (size_t)QKV_E;

    // 0) one-time split conversions (x -> tail scratch, weights -> bss)
    cvt_split<<<6144, 256>>>(x, xhi, xlo, 0, 1572864);
    cvt_split<<<1728, 256>>>(w_qkv, nullptr, nullptr, 1, 442368);
    cvt_split<<<576, 256>>>(w_proj, nullptr, nullptr, 2, 147456);

    // 1) QKV projection (pre-split operands) -> bf16 hi/lo scratch
    gemm_mma<0><<<dim3(C3 / 128, MROWS / 128), 256>>>(
        xhi, xlo, nullptr, scr, nullptr);

    // 2) stash q/k/v of batches 6,7 into bss
    copy67<<<1536, 256>>>(scr);

    // 3) attention, batches 0..5 (bh 0..71)
    score_mma  <<<dim3(8, 8, 72), 256>>>(scr, attn, 0);
    softmax_all<<<dim3(128, 72), 256>>>(attn);
    pv_mma     <<<dim3(8, 72), 256>>>(attn, scr, 0, 0);

    // 4) attention, batches 6,7 from the bss stash
    float* attn67 = attn + 72 * (size_t)PSTRIDE;
    score_mma  <<<dim3(8, 8, 24), 256>>>(nullptr, attn67, 1);
    softmax_all<<<dim3(128, 24), 256>>>(attn67);
    pv_mma     <<<dim3(8, 24), 256>>>(attn67, nullptr, 72, 1);

    // 5) output projection (pre-split operands)
    gemm_mma<1><<<dim3(NC / 128, MROWS / 128), 256>>>(
        nullptr, nullptr, b_proj, nullptr, out);
}

// round 14
// speedup vs baseline: 3.8896x; 1.0642x over previous
#include <cuda_runtime.h>
#include <cuda_bf16.h>
#include <cstdint>

// Problem constants
#define NB 8
#define NN 1024
#define NC 768
#define NH 12
#define ND 64
#define C3 2304
#define MROWS 8192
#define SCALE 0.125f

#define OUT_ELEMS  6291456
#define ATTN_ELEMS 100663296
#define TOTAL_ELEMS 106954752
#define BHD 65536               // NN*ND
#define PSTRIDE 1048576         // NN*NN
#define QKV_E 6291456           // NB*NH*NN*ND elements per q/k/v array
#define SCR_BASE 75497472       // 72*PSTRIDE

// bss: O hi/lo 25MB + stash 19MB + weights 9.5MB ~ 53MB (16B aligned for cp.async)
__device__ __align__(16) __nv_bfloat16 g_oh[(size_t)MROWS * NC];
__device__ __align__(16) __nv_bfloat16 g_ol[(size_t)MROWS * NC];
__device__ __align__(16) __nv_bfloat16 g_wqh[(size_t)C3 * NC];
__device__ __align__(16) __nv_bfloat16 g_wql[(size_t)C3 * NC];
__device__ __align__(16) __nv_bfloat16 g_wph[(size_t)NC * NC];
__device__ __align__(16) __nv_bfloat16 g_wpl[(size_t)NC * NC];
__device__ __align__(16) float g_q2[2 * NH * NN * ND];   // QHi|QLo stash b=6,7
__device__ __align__(16) float g_k2[2 * NH * NN * ND];
__device__ __align__(16) float g_v2[2 * NH * NN * ND];

__device__ __forceinline__ float4 ld4(const float* p) { return *(const float4*)p; }

__device__ __forceinline__ uint32_t s2u(const void* p) {
    uint32_t a;
    asm("{ .reg .u64 t; cvta.to.shared.u64 t, %1; cvt.u32.u64 %0, t; }"
        : "=r"(a) : "l"(p));
    return a;
}

__device__ __forceinline__ void mma16816(float* d, const uint32_t* a,
                                         const uint32_t* b) {
    asm volatile(
        "mma.sync.aligned.m16n8k16.row.col.f32.bf16.bf16.f32 "
        "{%0,%1,%2,%3}, {%4,%5,%6,%7}, {%8,%9}, {%0,%1,%2,%3};"
        : "+f"(d[0]), "+f"(d[1]), "+f"(d[2]), "+f"(d[3])
        : "r"(a[0]), "r"(a[1]), "r"(a[2]), "r"(a[3]), "r"(b[0]), "r"(b[1]));
}
__device__ __forceinline__ void ldmx4(uint32_t* r, uint32_t addr) {
    asm volatile("ldmatrix.sync.aligned.m8n8.x4.shared.b16 {%0,%1,%2,%3}, [%4];"
                 : "=r"(r[0]), "=r"(r[1]), "=r"(r[2]), "=r"(r[3]) : "r"(addr));
}
__device__ __forceinline__ void ldmx4t(uint32_t* r, uint32_t addr) {
    asm volatile("ldmatrix.sync.aligned.m8n8.x4.trans.shared.b16 {%0,%1,%2,%3}, [%4];"
                 : "=r"(r[0]), "=r"(r[1]), "=r"(r[2]), "=r"(r[3]) : "r"(addr));
}
__device__ __forceinline__ void cpa16(uint32_t dst, const void* src) {
    asm volatile("cp.async.cg.shared.global [%0], [%1], 16;"
                 :: "r"(dst), "l"(src));
}
#define CP_COMMIT() asm volatile("cp.async.commit_group;")
#define CP_WAIT0()  asm volatile("cp.async.wait_group 0;" ::: "memory")

// Fast Dekker split: hi = bf16-truncate(x), lo = rn(x - hi).
__device__ __forceinline__ void split2(float x0, float x1,
                                       uint32_t& hi, uint32_t& lo) {
    const uint32_t u0 = __float_as_uint(x0), u1 = __float_as_uint(x1);
    hi = __byte_perm(u0, u1, 0x7632);
    const float h0f = __uint_as_float(u0 & 0xFFFF0000u);
    const float h1f = __uint_as_float(u1 & 0xFFFF0000u);
    const float l0 = x0 - h0f, l1 = x1 - h1f;
    asm("cvt.rn.bf16x2.f32 %0, %1, %2;" : "=r"(lo) : "f"(l1), "f"(l0));
}

// ---------------------------------------------------------------------------
// Split-convert fp32 array -> bf16 hi/lo arrays.
// ---------------------------------------------------------------------------
__global__ __launch_bounds__(256)
void cvt_split(const float* __restrict__ src, __nv_bfloat16* hi_arg,
               __nv_bfloat16* lo_arg, int dst_sel, int n4)
{
    __nv_bfloat16* hi = hi_arg;
    __nv_bfloat16* lo = lo_arg;
    if (dst_sel == 1) { hi = g_wqh; lo = g_wql; }
    else if (dst_sel == 2) { hi = g_wph; lo = g_wpl; }
    const int i = blockIdx.x * blockDim.x + threadIdx.x;
    if (i < n4) {
        const float4 v = ((const float4*)src)[i];
        uint32_t h0, l0, h1, l1;
        split2(v.x, v.y, h0, l0);
        split2(v.z, v.w, h1, l1);
        ((uint2*)hi)[i] = make_uint2(h0, h1);
        ((uint2*)lo)[i] = make_uint2(l0, l1);
    }
}

// ---------------------------------------------------------------------------
// mma.sync GEMM on pre-split bf16 operands, cp.async tile loads, 2 CTAs/SM.
// 128x128 CTA tile, BK=32, 256 threads = 8 warps (2x4), warp tile 64x32.
// MODE 0: A = x hi/lo, W = g_wqh/l -> q/k/v bf16 hi/lo scratch (q pre-scaled).
// MODE 1: A = g_oh/l, W = g_wph/l (+bias) -> fp32 out.
// ---------------------------------------------------------------------------
template <int MODE>
__global__ __launch_bounds__(256, 2)
void gemm_mma(const __nv_bfloat16* __restrict__ xhi,
              const __nv_bfloat16* __restrict__ xlo,
              const float* __restrict__ bias,
              __nv_bfloat16* __restrict__ scr, float* __restrict__ out)
{
    __shared__ __align__(16) __nv_bfloat16 Ah[128][40];
    __shared__ __align__(16) __nv_bfloat16 Al[128][40];
    __shared__ __align__(16) __nv_bfloat16 Bh[128][40];
    __shared__ __align__(16) __nv_bfloat16 Bl[128][40];

    const int tid  = threadIdx.x;
    const int lane = tid & 31, wid = tid >> 5;
    const int wm = wid >> 2, wn = wid & 3;
    const int m0 = blockIdx.y * 128, n0 = blockIdx.x * 128;

    const __nv_bfloat16 *Ahi, *Alo, *Whi, *Wlo;
    if (MODE == 0) { Ahi = xhi;  Alo = xlo;  Whi = g_wqh; Wlo = g_wql; }
    else           { Ahi = g_oh; Alo = g_ol; Whi = g_wph; Wlo = g_wpl; }

    float acc[4][4][4];
#pragma unroll
    for (int mi = 0; mi < 4; ++mi)
#pragma unroll
        for (int ni = 0; ni < 4; ++ni)
#pragma unroll
            for (int q = 0; q < 4; ++q) acc[mi][ni][q] = 0.0f;

    const uint32_t uAh = s2u(Ah), uAl = s2u(Al);
    const uint32_t uBh = s2u(Bh), uBl = s2u(Bl);

    const int arow = lane & 15;
    const int acol = (lane >> 4) * 8;
    uint32_t aoff[4];
#pragma unroll
    for (int mi = 0; mi < 4; ++mi)
        aoff[mi] = (uint32_t)(((wm * 64 + mi * 16 + arow) * 40 + acol) * 2);
    const int brow = wn * 32 + ((lane >> 4) * 8) + (lane & 7);
    const int bcol = ((lane >> 3) & 1) * 8;
    uint32_t boff[2];
#pragma unroll
    for (int g = 0; g < 2; ++g)
        boff[g] = (uint32_t)(((brow + g * 16) * 40 + bcol) * 2);

    // cp.async loader: thread -> 2 chunks per array (rows 0-63, 64-127)
    const int lrow0 = tid >> 2;          // 0..63
    const int lcol0 = (tid & 3) * 8;     // 0,8,16,24

    for (int kt = 0; kt < 24; ++kt) {
        if (kt) __syncthreads();          // prior compute done with smem
#pragma unroll
        for (int it = 0; it < 2; ++it) {
            const int row = lrow0 + it * 64;
            const size_t ga = (size_t)(m0 + row) * NC + kt * 32 + lcol0;
            const size_t gw = (size_t)(n0 + row) * NC + kt * 32 + lcol0;
            const uint32_t so = (uint32_t)((row * 40 + lcol0) * 2);
            cpa16(uAh + so, Ahi + ga);
            cpa16(uAl + so, Alo + ga);
            cpa16(uBh + so, Whi + gw);
            cpa16(uBl + so, Wlo + gw);
        }
        CP_COMMIT();
        CP_WAIT0();
        __syncthreads();

#pragma unroll
        for (int ks = 0; ks < 2; ++ks) {
            const uint32_t ko = (uint32_t)(ks * 32);
            uint32_t ah[4][4], al[4][4], bb[2][4];
#pragma unroll
            for (int mi = 0; mi < 4; ++mi) ldmx4(ah[mi], uAh + aoff[mi] + ko);
#pragma unroll
            for (int g = 0; g < 2; ++g) ldmx4(bb[g], uBh + boff[g] + ko);
#pragma unroll
            for (int mi = 0; mi < 4; ++mi) {
                mma16816(acc[mi][0], ah[mi], &bb[0][0]);
                mma16816(acc[mi][1], ah[mi], &bb[0][2]);
                mma16816(acc[mi][2], ah[mi], &bb[1][0]);
                mma16816(acc[mi][3], ah[mi], &bb[1][2]);
            }
#pragma unroll
            for (int mi = 0; mi < 4; ++mi) ldmx4(al[mi], uAl + aoff[mi] + ko);
#pragma unroll
            for (int mi = 0; mi < 4; ++mi) {
                mma16816(acc[mi][0], al[mi], &bb[0][0]);
                mma16816(acc[mi][1], al[mi], &bb[0][2]);
                mma16816(acc[mi][2], al[mi], &bb[1][0]);
                mma16816(acc[mi][3], al[mi], &bb[1][2]);
            }
#pragma unroll
            for (int g = 0; g < 2; ++g) ldmx4(bb[g], uBl + boff[g] + ko);
#pragma unroll
            for (int mi = 0; mi < 4; ++mi) {
                mma16816(acc[mi][0], ah[mi], &bb[0][0]);
                mma16816(acc[mi][1], ah[mi], &bb[0][2]);
                mma16816(acc[mi][2], ah[mi], &bb[1][0]);
                mma16816(acc[mi][3], ah[mi], &bb[1][2]);
            }
        }
    }

    const int erow = lane >> 2;
    const int ecol = (lane & 3) * 2;
#pragma unroll
    for (int ni = 0; ni < 4; ++ni) {
        const int gc = n0 + wn * 32 + ni * 8 + ecol;
        if (MODE == 0) {
            const int s   = gc / NC;
            const int rem = gc % NC;
            const int h   = rem >> 6;
            const int d   = rem & 63;
            const float sc = (s == 0) ? SCALE : 1.0f;   // pre-scale q (exact)
            __nv_bfloat16* dh = scr + (size_t)(2 * s) * QKV_E;
            __nv_bfloat16* dl = dh + QKV_E;
#pragma unroll
            for (int mi = 0; mi < 4; ++mi) {
                const int gr = m0 + wm * 64 + mi * 16 + erow;
#pragma unroll
                for (int half = 0; half < 2; ++half) {
                    const int r = gr + half * 8;
                    const int b = r >> 10, nn = r & 1023;
                    const size_t off = ((size_t)(b * NH + h) * NN + nn) * ND + d;
                    uint32_t hw, lw;
                    split2(acc[mi][ni][half * 2] * sc,
                           acc[mi][ni][half * 2 + 1] * sc, hw, lw);
                    *(uint32_t*)(dh + off) = hw;
                    *(uint32_t*)(dl + off) = lw;
                }
            }
        } else {
            const float2 bv = *(const float2*)(bias + gc);
#pragma unroll
            for (int mi = 0; mi < 4; ++mi) {
                const int gr = m0 + wm * 64 + mi * 16 + erow;
#pragma unroll
                for (int half = 0; half < 2; ++half) {
                    float* p = out + (size_t)(gr + half * 8) * NC + gc;
                    *(float2*)p = make_float2(acc[mi][ni][half * 2] + bv.x,
                                              acc[mi][ni][half * 2 + 1] + bv.y);
                }
            }
        }
    }
}

// ---------------------------------------------------------------------------
// Stash bf16 q/k/v of batches 6,7 (bh 72..95) into bss.
// ---------------------------------------------------------------------------
__global__ __launch_bounds__(256)
void copy67(const __nv_bfloat16* __restrict__ scr)
{
    const int n = 24 * BHD / 8;     // uint4 per segment
    const uint4* qh = (const uint4*)(scr + 72 * (size_t)BHD);
    const uint4* ql = (const uint4*)(scr + (size_t)QKV_E + 72 * (size_t)BHD);
    const uint4* kh = (const uint4*)(scr + 2 * (size_t)QKV_E + 72 * (size_t)BHD);
    const uint4* kl = (const uint4*)(scr + 3 * (size_t)QKV_E + 72 * (size_t)BHD);
    const uint4* vh = (const uint4*)(scr + 4 * (size_t)QKV_E + 72 * (size_t)BHD);
    const uint4* vl = (const uint4*)(scr + 5 * (size_t)QKV_E + 72 * (size_t)BHD);
    uint4* dq = (uint4*)g_q2;
    uint4* dk = (uint4*)g_k2;
    uint4* dv = (uint4*)g_v2;
    for (int i = blockIdx.x * blockDim.x + threadIdx.x; i < n;
         i += gridDim.x * blockDim.x) {
        dq[i] = qh[i]; dq[n + i] = ql[i];
        dk[i] = kh[i]; dk[n + i] = kl[i];
        dv[i] = vh[i]; dv[n + i] = vl[i];
    }
}

// ---------------------------------------------------------------------------
// Scores via mma.sync (q pre-scaled): P = q . k^T, split-3, cp.async loads.
// ---------------------------------------------------------------------------
__global__ __launch_bounds__(256, 2)
void score_mma(const __nv_bfloat16* __restrict__ scr,
               float* __restrict__ probs_base, int stash)
{
    __shared__ __align__(16) __nv_bfloat16 QHs[128][40], QLs[128][40];
    __shared__ __align__(16) __nv_bfloat16 KHs[128][40], KLs[128][40];

    const int tid  = threadIdx.x;
    const int lane = tid & 31, wid = tid >> 5;
    const int wm = wid >> 2, wn = wid & 3;
    const int m0 = blockIdx.y * 128, n0 = blockIdx.x * 128;
    const int z  = blockIdx.z;

    const __nv_bfloat16 *qh, *ql, *kh, *kl;
    if (stash) {
        qh = (const __nv_bfloat16*)g_q2; ql = qh + 24 * (size_t)BHD;
        kh = (const __nv_bfloat16*)g_k2; kl = kh + 24 * (size_t)BHD;
    } else {
        qh = scr;                        ql = scr + (size_t)QKV_E;
        kh = scr + 2 * (size_t)QKV_E;    kl = scr + 3 * (size_t)QKV_E;
    }
    qh += (size_t)z * BHD; ql += (size_t)z * BHD;
    kh += (size_t)z * BHD; kl += (size_t)z * BHD;

    float acc[4][4][4];
#pragma unroll
    for (int mi = 0; mi < 4; ++mi)
#pragma unroll
        for (int ni = 0; ni < 4; ++ni)
#pragma unroll
            for (int q = 0; q < 4; ++q) acc[mi][ni][q] = 0.0f;

    const uint32_t uQh = s2u(QHs), uQl = s2u(QLs);
    const uint32_t uKh = s2u(KHs), uKl = s2u(KLs);

    const int arow = lane & 15;
    const int acol = (lane >> 4) * 8;
    uint32_t aoff[4];
#pragma unroll
    for (int mi = 0; mi < 4; ++mi)
        aoff[mi] = (uint32_t)(((wm * 64 + mi * 16 + arow) * 40 + acol) * 2);
    const int brow = wn * 32 + ((lane >> 4) * 8) + (lane & 7);
    const int bcol = ((lane >> 3) & 1) * 8;
    uint32_t boff[2];
#pragma unroll
    for (int g = 0; g < 2; ++g)
        boff[g] = (uint32_t)(((brow + g * 16) * 40 + bcol) * 2);

    const int lrow0 = tid >> 2;
    const int lcol0 = (tid & 3) * 8;

#pragma unroll
    for (int kt = 0; kt < 2; ++kt) {
        if (kt) __syncthreads();
#pragma unroll
        for (int it = 0; it < 2; ++it) {
            const int row = lrow0 + it * 64;
            const int kc  = kt * 32 + lcol0;
            const size_t gq = (size_t)(m0 + row) * ND + kc;
            const size_t gk = (size_t)(n0 + row) * ND + kc;
            const uint32_t so = (uint32_t)((row * 40 + lcol0) * 2);
            cpa16(uQh + so, qh + gq);
            cpa16(uQl + so, ql + gq);
            cpa16(uKh + so, kh + gk);
            cpa16(uKl + so, kl + gk);
        }
        CP_COMMIT();
        CP_WAIT0();
        __syncthreads();

#pragma unroll
        for (int ks = 0; ks < 2; ++ks) {
            const uint32_t ko = (uint32_t)(ks * 32);
            uint32_t ah[4][4], al[4][4], bb[2][4];
#pragma unroll
            for (int mi = 0; mi < 4; ++mi) ldmx4(ah[mi], uQh + aoff[mi] + ko);
#pragma unroll
            for (int g = 0; g < 2; ++g) ldmx4(bb[g], uKh + boff[g] + ko);
#pragma unroll
            for (int mi = 0; mi < 4; ++mi) {
                mma16816(acc[mi][0], ah[mi], &bb[0][0]);
                mma16816(acc[mi][1], ah[mi], &bb[0][2]);
                mma16816(acc[mi][2], ah[mi], &bb[1][0]);
                mma16816(acc[mi][3], ah[mi], &bb[1][2]);
            }
#pragma unroll
            for (int mi = 0; mi < 4; ++mi) ldmx4(al[mi], uQl + aoff[mi] + ko);
#pragma unroll
            for (int mi = 0; mi < 4; ++mi) {
                mma16816(acc[mi][0], al[mi], &bb[0][0]);
                mma16816(acc[mi][1], al[mi], &bb[0][2]);
                mma16816(acc[mi][2], al[mi], &bb[1][0]);
                mma16816(acc[mi][3], al[mi], &bb[1][2]);
            }
#pragma unroll
            for (int g = 0; g < 2; ++g) ldmx4(bb[g], uKl + boff[g] + ko);
#pragma unroll
            for (int mi = 0; mi < 4; ++mi) {
                mma16816(acc[mi][0], ah[mi], &bb[0][0]);
                mma16816(acc[mi][1], ah[mi], &bb[0][2]);
                mma16816(acc[mi][2], ah[mi], &bb[1][0]);
                mma16816(acc[mi][3], ah[mi], &bb[1][2]);
            }
        }
    }

    float* outp = probs_base + (size_t)z * PSTRIDE;
    const int erow = lane >> 2;
    const int ecol = (lane & 3) * 2;
#pragma unroll
    for (int ni = 0; ni < 4; ++ni) {
        const int gc = n0 + wn * 32 + ni * 8 + ecol;
#pragma unroll
        for (int mi = 0; mi < 4; ++mi) {
            const int gr = m0 + wm * 64 + mi * 16 + erow;
#pragma unroll
            for (int half = 0; half < 2; ++half) {
                float* p = outp + (size_t)(gr + half * 8) * NN + gc;
                *(float2*)p = make_float2(acc[mi][ni][half * 2],
                                          acc[mi][ni][half * 2 + 1]);
            }
        }
    }
}

// ---------------------------------------------------------------------------
// Softmax in place (at its DRAM roofline)
// ---------------------------------------------------------------------------
__global__ __launch_bounds__(256)
void softmax_all(float* __restrict__ probs_base)
{
    const int w    = threadIdx.x >> 5;
    const int lane = threadIdx.x & 31;
    const int z    = blockIdx.y;
    const int r    = blockIdx.x * 8 + w;

    float4* row = (float4*)(probs_base + (size_t)z * PSTRIDE + (size_t)r * NN);

    float4 v[8];
#pragma unroll
    for (int t = 0; t < 8; ++t) v[t] = row[lane + t * 32];

    float mx = -1e30f;
#pragma unroll
    for (int t = 0; t < 8; ++t)
        mx = fmaxf(mx, fmaxf(fmaxf(v[t].x, v[t].y), fmaxf(v[t].z, v[t].w)));
#pragma unroll
    for (int off = 16; off >= 1; off >>= 1)
        mx = fmaxf(mx, __shfl_xor_sync(0xffffffffu, mx, off));

    float sum = 0.0f;
#pragma unroll
    for (int t = 0; t < 8; ++t) {
        v[t].x = __expf(v[t].x - mx); v[t].y = __expf(v[t].y - mx);
        v[t].z = __expf(v[t].z - mx); v[t].w = __expf(v[t].w - mx);
        sum += v[t].x + v[t].y + v[t].z + v[t].w;
    }
#pragma unroll
    for (int off = 16; off >= 1; off >>= 1)
        sum += __shfl_xor_sync(0xffffffffu, sum, off);

    const float inv = 1.0f / sum;
#pragma unroll
    for (int t = 0; t < 8; ++t) {
        v[t].x *= inv; v[t].y *= inv; v[t].z *= inv; v[t].w *= inv;
        row[lane + t * 32] = v[t];
    }
}

// ---------------------------------------------------------------------------
// PV via mma.sync: O = P @ V, split-3; O written as bf16 hi/lo (g_oh/g_ol).
// Grid (8, Z), 256 threads = 8 warps (4x2), warp tile 32x32, BK=32.
// ---------------------------------------------------------------------------
__global__ __launch_bounds__(256, 2)
void pv_mma(const float* __restrict__ probs_base,
            const __nv_bfloat16* __restrict__ scr, int bh0, int stash)
{
    __shared__ __align__(16) __nv_bfloat16 PH[128][40], PL[128][40];
    __shared__ __align__(16) __nv_bfloat16 VHs[32][72], VLs[32][72];

    const int tid  = threadIdx.x;
    const int lane = tid & 31, wid = tid >> 5;
    const int wm = wid >> 1, wn = wid & 1;
    const int n0 = blockIdx.x * 128;
    const int z  = blockIdx.y;
    const int bh = bh0 + z;
    const int b  = bh / NH, h = bh % NH;

    const float* P = probs_base + (size_t)z * PSTRIDE + (size_t)n0 * NN;
    const __nv_bfloat16 *vh, *vl;
    if (stash) {
        vh = (const __nv_bfloat16*)g_v2; vl = vh + 24 * (size_t)BHD;
    } else {
        vh = scr + 4 * (size_t)QKV_E;    vl = scr + 5 * (size_t)QKV_E;
    }
    vh += (size_t)z * BHD; vl += (size_t)z * BHD;

    float acc[2][4][4];
#pragma unroll
    for (int mi = 0; mi < 2; ++mi)
#pragma unroll
        for (int ni = 0; ni < 4; ++ni)
#pragma unroll
            for (int q = 0; q < 4; ++q) acc[mi][ni][q] = 0.0f;

    const uint32_t uPH = s2u(PH), uPL = s2u(PL);
    const uint32_t uVH = s2u(VHs), uVL = s2u(VLs);

    const int arow = lane & 15;
    const int acol = (lane >> 4) * 8;
    uint32_t aoff[2];
#pragma unroll
    for (int mi = 0; mi < 2; ++mi)
        aoff[mi] = (uint32_t)(((wm * 32 + mi * 16 + arow) * 40 + acol) * 2);
    const int tk = (lane & 7) + ((lane >> 3) & 1) * 8;
    uint32_t boff[2];
#pragma unroll
    for (int g = 0; g < 2; ++g)
        boff[g] = (uint32_t)((tk * 72 + wn * 32 + g * 16 + ((lane >> 4) & 1) * 8) * 2);

    const int pr = tid >> 3, pc4 = (tid & 7) * 4;
    const int vr = tid >> 3, vc8 = (tid & 7) * 8;    // V: 16B cp.async chunks

    float4 pa[4];
#pragma unroll
    for (int it = 0; it < 4; ++it)
        pa[it] = ld4(P + (size_t)(pr + it * 32) * NN + pc4);

    for (int kt = 0; kt < 32; ++kt) {
        __syncthreads();
        // V tile via cp.async (32 rows x 64 cols, one 16B chunk per thread)
        {
            const size_t gv = (size_t)(kt * 32 + vr) * ND + vc8;
            const uint32_t so = (uint32_t)((vr * 72 + vc8) * 2);
            cpa16(uVH + so, vh + gv);
            cpa16(uVL + so, vl + gv);
        }
        // P tile: fp32 -> split in regs -> smem
#pragma unroll
        for (int it = 0; it < 4; ++it) {
            const int row = pr + it * 32;
            uint32_t h0, l0, h1, l1;
            split2(pa[it].x, pa[it].y, h0, l0);
            split2(pa[it].z, pa[it].w, h1, l1);
            *(uint2*)&PH[row][pc4] = make_uint2(h0, h1);
            *(uint2*)&PL[row][pc4] = make_uint2(l0, l1);
        }
        CP_COMMIT();
        CP_WAIT0();
        __syncthreads();
        if (kt < 31) {
#pragma unroll
            for (int it = 0; it < 4; ++it)
                pa[it] = ld4(P + (size_t)(pr + it * 32) * NN + (kt + 1) * 32 + pc4);
        }
#pragma unroll
        for (int ks = 0; ks < 2; ++ks) {
            const uint32_t ko_a = (uint32_t)(ks * 32);
            const uint32_t ko_b = (uint32_t)(ks * 16 * 72 * 2);
            uint32_t ah[2][4], al[2][4], bb[2][4];
#pragma unroll
            for (int mi = 0; mi < 2; ++mi) ldmx4(ah[mi], uPH + aoff[mi] + ko_a);
#pragma unroll
            for (int g = 0; g < 2; ++g) ldmx4t(bb[g], uVH + boff[g] + ko_b);
#pragma unroll
            for (int mi = 0; mi < 2; ++mi) {
                mma16816(acc[mi][0], ah[mi], &bb[0][0]);
                mma16816(acc[mi][1], ah[mi], &bb[0][2]);
                mma16816(acc[mi][2], ah[mi], &bb[1][0]);
                mma16816(acc[mi][3], ah[mi], &bb[1][2]);
            }
#pragma unroll
            for (int mi = 0; mi < 2; ++mi) ldmx4(al[mi], uPL + aoff[mi] + ko_a);
#pragma unroll
            for (int mi = 0; mi < 2; ++mi) {
                mma16816(acc[mi][0], al[mi], &bb[0][0]);
                mma16816(acc[mi][1], al[mi], &bb[0][2]);
                mma16816(acc[mi][2], al[mi], &bb[1][0]);
                mma16816(acc[mi][3], al[mi], &bb[1][2]);
            }
#pragma unroll
            for (int g = 0; g < 2; ++g) ldmx4t(bb[g], uVL + boff[g] + ko_b);
#pragma unroll
            for (int mi = 0; mi < 2; ++mi) {
                mma16816(acc[mi][0], ah[mi], &bb[0][0]);
                mma16816(acc[mi][1], ah[mi], &bb[0][2]);
                mma16816(acc[mi][2], ah[mi], &bb[1][0]);
                mma16816(acc[mi][3], ah[mi], &bb[1][2]);
            }
        }
    }

    const int erow = lane >> 2;
    const int ecol = (lane & 3) * 2;
#pragma unroll
    for (int ni = 0; ni < 4; ++ni) {
        const int d = wn * 32 + ni * 8 + ecol;
#pragma unroll
        for (int mi = 0; mi < 2; ++mi) {
            const int gr = n0 + wm * 32 + mi * 16 + erow;
#pragma unroll
            for (int half = 0; half < 2; ++half) {
                const size_t off = ((size_t)b * NN + gr + half * 8) * NC + h * ND + d;
                uint32_t hw, lw;
                split2(acc[mi][ni][half * 2], acc[mi][ni][half * 2 + 1], hw, lw);
                *(uint32_t*)(g_oh + off) = hw;
                *(uint32_t*)(g_ol + off) = lw;
            }
        }
    }
}

// ---------------------------------------------------------------------------
extern "C" void kernel_launch(void* const* d_in, const int* in_sizes, int n_in,
                              void* d_out, int out_size)
{
    const float* x      = (n_in > 0) ? (const float*)d_in[0] : nullptr;
    const float* w_qkv  = (n_in > 1) ? (const float*)d_in[1] : nullptr;
    const float* w_proj = (n_in > 2) ? (const float*)d_in[2] : nullptr;
    const float* b_proj = (n_in > 3) ? (const float*)d_in[3] : nullptr;
    for (int i = 0; i < n_in; ++i) {
        const long long s = in_sizes[i];
        if (s == 6291456LL || s == 25165824LL)      x      = (const float*)d_in[i];
        else if (s == 1769472LL || s == 7077888LL)  w_qkv  = (const float*)d_in[i];
        else if (s == 589824LL  || s == 2359296LL)  w_proj = (const float*)d_in[i];
        else if (s == 768LL     || s == 3072LL)     b_proj = (const float*)d_in[i];
    }
    if (!x || !w_qkv || !w_proj || !b_proj) return;
    if (out_size < TOTAL_ELEMS) return;

    float* out  = (float*)d_out;
    float* attn = out + OUT_ELEMS;

    // attn-region tail: [QH|QL|KH|KL|VH|VL] bf16 scratch, then x hi/lo bf16.
    __nv_bfloat16* scr = (__nv_bfloat16*)(attn + SCR_BASE);
    __nv_bfloat16* xhi = scr + 6 * (size_t)QKV_E;
    __nv_bfloat16* xlo = xhi + (size_t)QKV_E;

    // 0) one-time split conversions
    cvt_split<<<6144, 256>>>(x, xhi, xlo, 0, 1572864);
    cvt_split<<<1728, 256>>>(w_qkv, nullptr, nullptr, 1, 442368);
    cvt_split<<<576, 256>>>(w_proj, nullptr, nullptr, 2, 147456);

    // 1) QKV projection -> bf16 hi/lo scratch (q pre-scaled by SCALE)
    gemm_mma<0><<<dim3(C3 / 128, MROWS / 128), 256>>>(
        xhi, xlo, nullptr, scr, nullptr);

    // 2) stash q/k/v of batches 6,7 into bss
    copy67<<<1536, 256>>>(scr);

    // 3) attention, batches 0..5 (bh 0..71)
    score_mma  <<<dim3(8, 8, 72), 256>>>(scr, attn, 0);
    softmax_all<<<dim3(128, 72), 256>>>(attn);
    pv_mma     <<<dim3(8, 72), 256>>>(attn, scr, 0, 0);

    // 4) attention, batches 6,7 from the bss stash
    float* attn67 = attn + 72 * (size_t)PSTRIDE;
    score_mma  <<<dim3(8, 8, 24), 256>>>(nullptr, attn67, 1);
    softmax_all<<<dim3(128, 24), 256>>>(attn67);
    pv_mma     <<<dim3(8, 24), 256>>>(attn67, nullptr, 72, 1);

    // 5) output projection
    gemm_mma<1><<<dim3(NC / 128, MROWS / 128), 256>>>(
        nullptr, nullptr, b_proj, nullptr, out);
}